// round 1
// baseline (speedup 1.0000x reference)
#include <cuda_runtime.h>
#include <math.h>

#define BSZ 8
#define CH 192
#define HWP 4096
#define WIDTH 64
#define MASKN 16

// ---- scratch (static device globals; no allocation in kernel_launch) ----
__device__ float g_b0[BSZ * CH * HWP];   // v, then dyn-conv output
__device__ float g_b1[BSZ * CH * HWP];   // x
__device__ float g_b2[BSZ * CH * HWP];   // y0
__device__ float g_b3[BSZ * CH * HWP];   // y1
__device__ float g_T[BSZ * MASKN * CH];
__device__ float g_mean[BSZ * CH];
__device__ float g_gate[BSZ * CH];

// ============================================================
// 1x1-conv GEMM over pixels: Y[b,co,p] = act( sum_ci W[co,ci]*X[b,ci,p] + bias
//                                             [+ T[b,mask[p],co]] ) [+ resid]
// BM=64, BN=64, BK=16, 256 threads, 4x4 microtile.
// ============================================================
template <bool LRELU, bool ADDT, bool FINAL>
__global__ __launch_bounds__(256) void gemm1x1_kernel(
    const float* __restrict__ X, const float* __restrict__ W,
    const float* __restrict__ bias, float* __restrict__ Y,
    int K, int wld,
    const int* __restrict__ mask, const float* __restrict__ Tt,
    const float* __restrict__ gate, const float* __restrict__ resid)
{
    __shared__ float As[16][68];   // padded: avoids 16-way STS bank conflict
    __shared__ float Bs[16][64];

    const int b  = blockIdx.z;
    const int m0 = blockIdx.y * 64;
    const int n0 = blockIdx.x * 64;
    const int tid = threadIdx.x;
    const int tm = tid >> 4;       // 0..15
    const int tn = tid & 15;       // 0..15

    const float* Xb = X + (size_t)b * K * HWP;

    float acc[4][4];
#pragma unroll
    for (int i = 0; i < 4; i++)
#pragma unroll
        for (int j = 0; j < 4; j++) acc[i][j] = 0.f;

    for (int kt = 0; kt < K; kt += 16) {
#pragma unroll
        for (int t = 0; t < 4; t++) {
            int idx = tid + t * 256;     // 0..1023
            int i = idx >> 4;            // m 0..63
            int j = idx & 15;            // k 0..15
            As[j][i] = W[(size_t)(m0 + i) * wld + kt + j];
        }
#pragma unroll
        for (int t = 0; t < 4; t++) {
            int idx = tid + t * 256;
            int j = idx >> 6;            // k 0..15
            int n = idx & 63;
            float v = Xb[(size_t)(kt + j) * HWP + n0 + n];
            if (FINAL) v *= gate[b * CH + kt + j];
            Bs[j][n] = v;
        }
        __syncthreads();
#pragma unroll
        for (int kk = 0; kk < 16; kk++) {
            float4 a4 = *(const float4*)&As[kk][tm * 4];
            float4 b4 = *(const float4*)&Bs[kk][tn * 4];
            float av[4] = {a4.x, a4.y, a4.z, a4.w};
            float bv[4] = {b4.x, b4.y, b4.z, b4.w};
#pragma unroll
            for (int i = 0; i < 4; i++)
#pragma unroll
                for (int j = 0; j < 4; j++)
                    acc[i][j] = fmaf(av[i], bv[j], acc[i][j]);
        }
        __syncthreads();
    }

    int mvals[4];
    if (ADDT) {
#pragma unroll
        for (int j = 0; j < 4; j++)
            mvals[j] = mask[b * HWP + n0 + tn * 4 + j];
    }

#pragma unroll
    for (int i = 0; i < 4; i++) {
        int co = m0 + tm * 4 + i;
        float bi = bias[co];
        float4 ov;
        float* op = &ov.x;
#pragma unroll
        for (int j = 0; j < 4; j++) {
            int p = n0 + tn * 4 + j;
            float v = acc[i][j] + bi;
            if (ADDT) v += Tt[(b * MASKN + mvals[j]) * CH + co];
            if (LRELU) v = v > 0.f ? v : 0.1f * v;
            if (FINAL) v += resid[((size_t)b * CH + co) * HWP + p];
            op[j] = v;
        }
        *(float4*)&Y[((size_t)b * CH + co) * HWP + n0 + tn * 4] = ov;
    }
}

// ============================================================
// 3x3 conv as implicit GEMM: K = 192*9 (one ci per BK=9 step).
// Each n-tile (64 contiguous pixels) is exactly one image row.
// Epilogue: bias + lrelu (always).
// ============================================================
__global__ __launch_bounds__(256) void conv3x3_kernel(
    const float* __restrict__ X, const float* __restrict__ W,
    const float* __restrict__ bias, float* __restrict__ Y)
{
    __shared__ float As[9][68];
    __shared__ float Bs[9][64];

    const int b  = blockIdx.z;
    const int m0 = blockIdx.y * 64;
    const int h  = blockIdx.x;       // n-tile == image row
    const int n0 = h * 64;
    const int tid = threadIdx.x;
    const int tm = tid >> 4;
    const int tn = tid & 15;

    const float* Xb = X + (size_t)b * CH * HWP;

    float acc[4][4];
#pragma unroll
    for (int i = 0; i < 4; i++)
#pragma unroll
        for (int j = 0; j < 4; j++) acc[i][j] = 0.f;

    for (int ci = 0; ci < CH; ci++) {
        for (int idx = tid; idx < 576; idx += 256) {
            int i = idx / 9;
            int r = idx % 9;
            As[r][i] = W[(size_t)(m0 + i) * (CH * 9) + ci * 9 + r];
        }
        for (int idx = tid; idx < 576; idx += 256) {
            int r = idx >> 6;            // 0..8
            int n = idx & 63;
            int di = r / 3 - 1;
            int dj = r % 3 - 1;
            int hh = h + di;
            int ww = n + dj;
            float v = 0.f;
            if (hh >= 0 && hh < 64 && ww >= 0 && ww < 64)
                v = Xb[(size_t)ci * HWP + hh * 64 + ww];
            Bs[r][n] = v;
        }
        __syncthreads();
#pragma unroll
        for (int r = 0; r < 9; r++) {
            float4 a4 = *(const float4*)&As[r][tm * 4];
            float4 b4 = *(const float4*)&Bs[r][tn * 4];
            float av[4] = {a4.x, a4.y, a4.z, a4.w};
            float bv[4] = {b4.x, b4.y, b4.z, b4.w};
#pragma unroll
            for (int i = 0; i < 4; i++)
#pragma unroll
                for (int j = 0; j < 4; j++)
                    acc[i][j] = fmaf(av[i], bv[j], acc[i][j]);
        }
        __syncthreads();
    }

#pragma unroll
    for (int i = 0; i < 4; i++) {
        int co = m0 + tm * 4 + i;
        float bi = bias[co];
        float4 ov;
        float* op = &ov.x;
#pragma unroll
        for (int j = 0; j < 4; j++) {
            float v = acc[i][j] + bi;
            op[j] = v > 0.f ? v : 0.1f * v;
        }
        *(float4*)&Y[((size_t)b * CH + co) * HWP + n0 + tn * 4] = ov;
    }
}

// ============================================================
// T[b,m,co] = sum_ci ws0[co, 192+ci] * list_center[b,m,ci]
// ============================================================
__global__ __launch_bounds__(192) void tgen_kernel(
    const float* __restrict__ lc, const float* __restrict__ ws0,
    float* __restrict__ T)
{
    __shared__ float c[CH];
    int bm = blockIdx.x;               // b*16 + m
    int co = threadIdx.x;
    c[co] = lc[(size_t)bm * CH + co];
    __syncthreads();
    float s = 0.f;
    const float* wrow = ws0 + (size_t)co * (CH * 2) + CH;
#pragma unroll 8
    for (int ci = 0; ci < CH; ci++) s = fmaf(wrow[ci], c[ci], s);
    T[bm * CH + co] = s;
}

// ============================================================
// Fused depthwise-3x3 (k_sp generation) + dynamic conv + mean reduce.
// One block per (b, c) plane.
// ============================================================
__global__ __launch_bounds__(256) void dyn_kernel(
    const float* __restrict__ Y1, const float* __restrict__ Xf,
    const float* __restrict__ ws2, const float* __restrict__ bs2,
    float* __restrict__ Out, float* __restrict__ Mean)
{
    __shared__ float sy[66 * 66];
    __shared__ float sx[66 * 66];
    __shared__ float taps[81];
    __shared__ float tb[9];
    __shared__ float red[256];

    const int c = blockIdx.x;
    const int b = blockIdx.y;
    const int tid = threadIdx.x;

    const float* y1p = Y1 + ((size_t)b * CH + c) * HWP;
    const float* xp  = Xf + ((size_t)b * CH + c) * HWP;

    for (int idx = tid; idx < 66 * 66; idx += 256) {
        int hh = idx / 66 - 1;
        int ww = idx % 66 - 1;
        bool ok = (hh >= 0 && hh < 64 && ww >= 0 && ww < 64);
        sy[idx] = ok ? y1p[hh * 64 + ww] : 0.f;
        sx[idx] = ok ? xp[hh * 64 + ww] : 0.f;
    }
    if (tid < 81) taps[tid] = ws2[c * 81 + tid];
    if (tid < 9)  tb[tid]   = bs2[c * 9 + tid];
    __syncthreads();

    float sum = 0.f;
    for (int pp = tid; pp < HWP; pp += 256) {
        int hq = pp >> 6;
        int wq = pp & 63;
        float ywin[9], xwin[9];
#pragma unroll
        for (int di = 0; di < 3; di++)
#pragma unroll
            for (int dj = 0; dj < 3; dj++) {
                ywin[di * 3 + dj] = sy[(hq + di) * 66 + (wq + dj)];
                xwin[di * 3 + dj] = sx[(hq + di) * 66 + (wq + dj)];
            }
        float o = 0.f;
#pragma unroll
        for (int kk = 0; kk < 9; kk++) {
            float ks = tb[kk];
#pragma unroll
            for (int r = 0; r < 9; r++)
                ks = fmaf(ywin[r], taps[kk * 9 + r], ks);
            o = fmaf(xwin[kk], ks, o);
        }
        Out[((size_t)b * CH + c) * HWP + pp] = o;
        sum += o;
    }
    red[tid] = sum;
    __syncthreads();
    for (int s = 128; s > 0; s >>= 1) {
        if (tid < s) red[tid] += red[tid + s];
        __syncthreads();
    }
    if (tid == 0) Mean[b * CH + c] = red[0] * (1.f / HWP);
}

// ============================================================
// SE gate: g = sigmoid(Wc1 * lrelu(Wc0 * mean + bc0) + bc1)
// ============================================================
__global__ __launch_bounds__(192) void se_kernel(
    const float* __restrict__ Mean,
    const float* __restrict__ wc0, const float* __restrict__ bc0,
    const float* __restrict__ wc1, const float* __restrict__ bc1,
    float* __restrict__ Gate)
{
    __shared__ float m[CH];
    __shared__ float hbuf[CH];
    int i = threadIdx.x;
    for (int b = 0; b < BSZ; b++) {
        m[i] = Mean[b * CH + i];
        __syncthreads();
        float s = bc0[i];
        const float* w = wc0 + (size_t)i * CH;
#pragma unroll 8
        for (int j = 0; j < CH; j++) s = fmaf(w[j], m[j], s);
        hbuf[i] = s > 0.f ? s : 0.1f * s;
        __syncthreads();
        float s2 = bc1[i];
        const float* w2 = wc1 + (size_t)i * CH;
#pragma unroll 8
        for (int j = 0; j < CH; j++) s2 = fmaf(w2[j], hbuf[j], s2);
        Gate[b * CH + i] = 1.f / (1.f + expf(-s2));
        __syncthreads();
    }
}

extern "C" void kernel_launch(void* const* d_in, const int* in_sizes, int n_in,
                              void* d_out, int out_size)
{
    const float* input = (const float*)d_in[0];
    const float* lc    = (const float*)d_in[1];
    const int*   mask  = (const int*)d_in[2];
    const float* w0  = (const float*)d_in[3];
    const float* b0  = (const float*)d_in[4];
    const float* w1  = (const float*)d_in[5];
    const float* b1  = (const float*)d_in[6];
    const float* ws0 = (const float*)d_in[7];
    const float* bs0 = (const float*)d_in[8];
    const float* ws1 = (const float*)d_in[9];
    const float* bs1 = (const float*)d_in[10];
    const float* ws2 = (const float*)d_in[11];
    const float* bs2 = (const float*)d_in[12];
    const float* wc0 = (const float*)d_in[13];
    const float* bc0 = (const float*)d_in[14];
    const float* wc1 = (const float*)d_in[15];
    const float* bc1 = (const float*)d_in[16];
    const float* wo  = (const float*)d_in[17];
    const float* bo  = (const float*)d_in[18];
    float* out = (float*)d_out;

    float *pb0, *pb1, *pb2, *pb3, *pT, *pMean, *pGate;
    cudaGetSymbolAddress((void**)&pb0, g_b0);
    cudaGetSymbolAddress((void**)&pb1, g_b1);
    cudaGetSymbolAddress((void**)&pb2, g_b2);
    cudaGetSymbolAddress((void**)&pb3, g_b3);
    cudaGetSymbolAddress((void**)&pT, g_T);
    cudaGetSymbolAddress((void**)&pMean, g_mean);
    cudaGetSymbolAddress((void**)&pGate, g_gate);

    dim3 grid(64, 3, 8), blk(256);

    // 1) v = lrelu(conv1x1(input, w0, b0))
    gemm1x1_kernel<true, false, false><<<grid, blk>>>(
        input, w0, b0, pb0, 192, 192, nullptr, nullptr, nullptr, nullptr);
    // 2) x = conv1x1(v, w1, b1)
    gemm1x1_kernel<false, false, false><<<grid, blk>>>(
        pb0, w1, b1, pb1, 192, 192, nullptr, nullptr, nullptr, nullptr);
    // 3) T table (center-half of ws0 applied to list_center)
    tgen_kernel<<<BSZ * MASKN, 192>>>(lc, ws0, pT);
    // 4) y0 = lrelu(ws0_x * x + T[b,mask] + bs0)
    gemm1x1_kernel<true, true, false><<<grid, blk>>>(
        pb1, ws0, bs0, pb2, 192, 384, mask, pT, nullptr, nullptr);
    // 5) y1 = lrelu(conv3x3(y0, ws1, bs1))
    conv3x3_kernel<<<grid, blk>>>(pb2, ws1, bs1, pb3);
    // 6) out_feat = dynamic_conv(x, depthwise(y1)) ; also per-(b,c) mean
    dyn_kernel<<<dim3(CH, BSZ), 256>>>(pb3, pb1, ws2, bs2, pb0, pMean);
    // 7) gate
    se_kernel<<<1, 192>>>(pMean, wc0, bc0, wc1, bc1, pGate);
    // 8) out = conv1x1(gate*out_feat, wo, bo) + input
    gemm1x1_kernel<false, false, true><<<grid, blk>>>(
        pb0, wo, bo, out, 192, 192, nullptr, nullptr, pGate, input);
}

// round 2
// speedup vs baseline: 2.3740x; 2.3740x over previous
#include <cuda_runtime.h>
#include <math.h>
#include <stdint.h>

#define BSZ 8
#define CH 192
#define HWP 4096
#define MASKN 16

// ---- scratch (static device globals; no allocation in kernel_launch) ----
__device__ float g_b0[BSZ * CH * HWP];   // v, then dyn-conv output
__device__ float g_b1[BSZ * CH * HWP];   // x
__device__ float g_b2[BSZ * CH * HWP];   // y0
__device__ float g_b3[BSZ * CH * HWP];   // y1
__device__ float g_wr[9 * CH * CH];      // reordered ws1: [r][co][ci]
__device__ float g_T[BSZ * MASKN * CH];
__device__ float g_mean[BSZ * CH];
__device__ float g_gate[BSZ * CH];

// ============================================================
// tf32 tensor-core mma m16n8k8 (row.col): D[16x8] += A[16x8]*B[8x8]
// ============================================================
__device__ __forceinline__ void mma_tf32(float* c, const uint32_t* a, const uint32_t* b)
{
    asm("mma.sync.aligned.m16n8k8.row.col.f32.tf32.tf32.f32 "
        "{%0,%1,%2,%3}, {%4,%5,%6,%7}, {%8,%9}, {%0,%1,%2,%3};\n"
        : "+f"(c[0]), "+f"(c[1]), "+f"(c[2]), "+f"(c[3])
        : "r"(a[0]), "r"(a[1]), "r"(a[2]), "r"(a[3]), "r"(b[0]), "r"(b[1]));
}

// ============================================================
// 1x1 conv as GEMM on tensor cores.
// D[co, p] = sum_ci W[co,ci] * X[b,ci,p]   (+bias, +T[b,mask[p],co], act, +resid)
// CTA: BM=64 (co), BN=256 (pixels), BK=16.  8 warps = 2(m) x 4(n).
// Warp tile 32x64 -> 2 m16 tiles x 8 n8 tiles.
// ============================================================
template <bool LRELU, bool ADDT, bool FINAL>
__global__ __launch_bounds__(256) void gemm1x1_tc(
    const float* __restrict__ X, const float* __restrict__ W,
    const float* __restrict__ bias, float* __restrict__ Y,
    int wld,
    const int* __restrict__ mask, const float* __restrict__ Tt,
    const float* __restrict__ gate, const float* __restrict__ resid)
{
    __shared__ float As[64][20];     // [m][k], stride 20: frag loads conflict-free
    __shared__ float Bs[16][264];    // [k][n], stride 264: frag loads conflict-free

    const int b   = blockIdx.z;
    const int m0  = blockIdx.y * 64;
    const int n0  = blockIdx.x * 256;
    const int tid = threadIdx.x;
    const int lane = tid & 31;
    const int warp = tid >> 5;
    const int wm = warp >> 2;        // 0..1
    const int wn = warp & 3;         // 0..3

    const float* Xb = X + (size_t)b * CH * HWP;

    float c[2][8][4];
#pragma unroll
    for (int i = 0; i < 2; i++)
#pragma unroll
        for (int j = 0; j < 8; j++)
#pragma unroll
            for (int q = 0; q < 4; q++) c[i][j][q] = 0.f;

    for (int kt = 0; kt < CH; kt += 16) {
        // A tile: W[m0+i][kt+j], 64x16
        {
            int i = tid >> 2, j0 = (tid & 3) * 4;
            float4 v = *(const float4*)(W + (size_t)(m0 + i) * wld + kt + j0);
            *(float4*)&As[i][j0] = v;
        }
        // B tile: X[kt+k][n0 + n], 16x256
        {
            int nb = (tid & 63) * 4;
#pragma unroll
            for (int q = 0; q < 4; q++) {
                int k = (tid >> 6) + q * 4;
                float4 v = *(const float4*)(Xb + (size_t)(kt + k) * HWP + n0 + nb);
                if (FINAL) {
                    float g = gate[b * CH + kt + k];
                    v.x *= g; v.y *= g; v.z *= g; v.w *= g;
                }
                *(float4*)&Bs[k][nb] = v;
            }
        }
        __syncthreads();

#pragma unroll
        for (int ks = 0; ks < 2; ks++) {
            const int kk = ks * 8 + (lane & 3);
            uint32_t a[2][4];
#pragma unroll
            for (int mt = 0; mt < 2; mt++) {
                int row = wm * 32 + mt * 16 + (lane >> 2);
                a[mt][0] = __float_as_uint(As[row][kk]);
                a[mt][1] = __float_as_uint(As[row + 8][kk]);
                a[mt][2] = __float_as_uint(As[row][kk + 4]);
                a[mt][3] = __float_as_uint(As[row + 8][kk + 4]);
            }
#pragma unroll
            for (int nt = 0; nt < 8; nt++) {
                int n = wn * 64 + nt * 8 + (lane >> 2);
                uint32_t bf[2];
                bf[0] = __float_as_uint(Bs[kk][n]);
                bf[1] = __float_as_uint(Bs[kk + 4][n]);
                mma_tf32(c[0][nt], a[0], bf);
                mma_tf32(c[1][nt], a[1], bf);
            }
        }
        __syncthreads();
    }

    // epilogue
#pragma unroll
    for (int mt = 0; mt < 2; mt++) {
        int cob = m0 + wm * 32 + mt * 16 + (lane >> 2);
#pragma unroll
        for (int half = 0; half < 2; half++) {
            int co = cob + half * 8;
            float bi = bias[co];
#pragma unroll
            for (int nt = 0; nt < 8; nt++) {
                int p = n0 + wn * 64 + nt * 8 + (lane & 3) * 2;
                float v0 = c[mt][nt][half * 2 + 0] + bi;
                float v1 = c[mt][nt][half * 2 + 1] + bi;
                if (ADDT) {
                    int mk0 = mask[b * HWP + p];
                    int mk1 = mask[b * HWP + p + 1];
                    v0 += Tt[(b * MASKN + mk0) * CH + co];
                    v1 += Tt[(b * MASKN + mk1) * CH + co];
                }
                if (LRELU) {
                    v0 = v0 > 0.f ? v0 : 0.1f * v0;
                    v1 = v1 > 0.f ? v1 : 0.1f * v1;
                }
                if (FINAL) {
                    v0 += resid[((size_t)b * CH + co) * HWP + p];
                    v1 += resid[((size_t)b * CH + co) * HWP + p + 1];
                }
                float2 o = make_float2(v0, v1);
                *(float2*)&Y[((size_t)b * CH + co) * HWP + p] = o;
            }
        }
    }
}

// ============================================================
// 3x3 conv on tensor cores (implicit GEMM).
// Per ci-chunk: load a zero-padded 6x66 halo patch ONCE, then run all
// 9 taps' MMAs directly against it with (di,dj)-offset fragment loads.
// A (weights) come pre-reordered as Wr[r][co][ci].
// CTA: BM=64, BN=256 (4 image rows), dynamic SMEM 72KB.
// ============================================================
__global__ __launch_bounds__(256) void conv3x3_tc(
    const float* __restrict__ X, const float* __restrict__ Wr,
    const float* __restrict__ bias, float* __restrict__ Y)
{
    extern __shared__ float smem[];
    float* As = smem;                      // [9][64][20] = 11520 floats
    float* Ps = smem + 9 * 64 * 20;        // [16][6][68] = 6528 floats

    const int b    = blockIdx.z;
    const int m0   = blockIdx.y * 64;
    const int tile = blockIdx.x;           // 0..15
    const int row0 = tile * 4;
    const int n0   = tile * 256;
    const int tid  = threadIdx.x;
    const int lane = tid & 31;
    const int warp = tid >> 5;
    const int wm = warp >> 2;
    const int wn = warp & 3;

    const float* Xb = X + (size_t)b * CH * HWP;

    float c[2][8][4];
#pragma unroll
    for (int i = 0; i < 2; i++)
#pragma unroll
        for (int j = 0; j < 8; j++)
#pragma unroll
            for (int q = 0; q < 4; q++) c[i][j][q] = 0.f;

    for (int kt = 0; kt < CH; kt += 16) {
        // 9 A tiles: Wr[r][m0+i][kt+j]   (2304 float4s, 9 per thread)
#pragma unroll
        for (int t = 0; t < 9; t++) {
            int idx = tid + t * 256;
            int r = idx >> 8;
            int rem = idx & 255;
            int i = rem >> 2, j0 = (rem & 3) * 4;
            float4 v = *(const float4*)(Wr + ((size_t)r * CH + m0 + i) * CH + kt + j0);
            *(float4*)&As[((r * 64) + i) * 20 + j0] = v;
        }
        // Halo patch: 16 ci x 6 rows x 66 cols, zero-padded
        for (int idx = tid; idx < 16 * 396; idx += 256) {
            int k = idx / 396;
            int rem = idx - k * 396;
            int rr = rem / 66;
            int cc = rem - rr * 66;
            int hh = row0 + rr - 1, ww = cc - 1;
            float v = 0.f;
            if (hh >= 0 && hh < 64 && ww >= 0 && ww < 64)
                v = Xb[(size_t)(kt + k) * HWP + hh * 64 + ww];
            Ps[(k * 6 + rr) * 68 + cc] = v;
        }
        __syncthreads();

        for (int r = 0; r < 9; r++) {
            int di = r / 3, dj = r - di * 3;      // 0..2
            const float* Ar = As + r * 64 * 20;
#pragma unroll
            for (int ks = 0; ks < 2; ks++) {
                const int kk = ks * 8 + (lane & 3);
                uint32_t a[2][4];
#pragma unroll
                for (int mt = 0; mt < 2; mt++) {
                    int row = wm * 32 + mt * 16 + (lane >> 2);
                    a[mt][0] = __float_as_uint(Ar[row * 20 + kk]);
                    a[mt][1] = __float_as_uint(Ar[(row + 8) * 20 + kk]);
                    a[mt][2] = __float_as_uint(Ar[row * 20 + kk + 4]);
                    a[mt][3] = __float_as_uint(Ar[(row + 8) * 20 + kk + 4]);
                }
#pragma unroll
                for (int nt = 0; nt < 8; nt++) {
                    int n = wn * 64 + nt * 8 + (lane >> 2);
                    int prow = (n >> 6) + di;
                    int pcol = (n & 63) + dj;
                    uint32_t bf[2];
                    bf[0] = __float_as_uint(Ps[(kk * 6 + prow) * 68 + pcol]);
                    bf[1] = __float_as_uint(Ps[((kk + 4) * 6 + prow) * 68 + pcol]);
                    mma_tf32(c[0][nt], a[0], bf);
                    mma_tf32(c[1][nt], a[1], bf);
                }
            }
        }
        __syncthreads();
    }

    // epilogue: bias + lrelu
#pragma unroll
    for (int mt = 0; mt < 2; mt++) {
        int cob = m0 + wm * 32 + mt * 16 + (lane >> 2);
#pragma unroll
        for (int half = 0; half < 2; half++) {
            int co = cob + half * 8;
            float bi = bias[co];
#pragma unroll
            for (int nt = 0; nt < 8; nt++) {
                int p = n0 + wn * 64 + nt * 8 + (lane & 3) * 2;
                float v0 = c[mt][nt][half * 2 + 0] + bi;
                float v1 = c[mt][nt][half * 2 + 1] + bi;
                v0 = v0 > 0.f ? v0 : 0.1f * v0;
                v1 = v1 > 0.f ? v1 : 0.1f * v1;
                float2 o = make_float2(v0, v1);
                *(float2*)&Y[((size_t)b * CH + co) * HWP + p] = o;
            }
        }
    }
}

// ============================================================
// Reorder ws1[co][ci][r] -> Wr[r][co][ci]
// ============================================================
__global__ void reorder_w(const float* __restrict__ ws1, float* __restrict__ wr)
{
    int idx = blockIdx.x * 256 + threadIdx.x;
    if (idx < 9 * CH * CH) {
        int ci = idx % CH;
        int co = (idx / CH) % CH;
        int r  = idx / (CH * CH);
        wr[idx] = ws1[(co * CH + ci) * 9 + r];
    }
}

// ============================================================
// T[b,m,co] = sum_ci ws0[co, 192+ci] * list_center[b,m,ci]
// ============================================================
__global__ __launch_bounds__(192) void tgen_kernel(
    const float* __restrict__ lc, const float* __restrict__ ws0,
    float* __restrict__ T)
{
    __shared__ float c[CH];
    int bm = blockIdx.x;
    int co = threadIdx.x;
    c[co] = lc[(size_t)bm * CH + co];
    __syncthreads();
    float s = 0.f;
    const float* wrow = ws0 + (size_t)co * (CH * 2) + CH;
#pragma unroll 8
    for (int ci = 0; ci < CH; ci++) s = fmaf(wrow[ci], c[ci], s);
    T[bm * CH + co] = s;
}

// ============================================================
// Fused depthwise-3x3 (k_sp generation) + dynamic conv + mean reduce.
// ============================================================
__global__ __launch_bounds__(256) void dyn_kernel(
    const float* __restrict__ Y1, const float* __restrict__ Xf,
    const float* __restrict__ ws2, const float* __restrict__ bs2,
    float* __restrict__ Out, float* __restrict__ Mean)
{
    __shared__ float sy[66 * 66];
    __shared__ float sx[66 * 66];
    __shared__ float taps[81];
    __shared__ float tb[9];
    __shared__ float red[256];

    const int c = blockIdx.x;
    const int b = blockIdx.y;
    const int tid = threadIdx.x;

    const float* y1p = Y1 + ((size_t)b * CH + c) * HWP;
    const float* xp  = Xf + ((size_t)b * CH + c) * HWP;

    for (int idx = tid; idx < 66 * 66; idx += 256) {
        int hh = idx / 66 - 1;
        int ww = idx % 66 - 1;
        bool ok = (hh >= 0 && hh < 64 && ww >= 0 && ww < 64);
        sy[idx] = ok ? y1p[hh * 64 + ww] : 0.f;
        sx[idx] = ok ? xp[hh * 64 + ww] : 0.f;
    }
    if (tid < 81) taps[tid] = ws2[c * 81 + tid];
    if (tid < 9)  tb[tid]   = bs2[c * 9 + tid];
    __syncthreads();

    float sum = 0.f;
    for (int pp = tid; pp < HWP; pp += 256) {
        int hq = pp >> 6;
        int wq = pp & 63;
        float ywin[9], xwin[9];
#pragma unroll
        for (int di = 0; di < 3; di++)
#pragma unroll
            for (int dj = 0; dj < 3; dj++) {
                ywin[di * 3 + dj] = sy[(hq + di) * 66 + (wq + dj)];
                xwin[di * 3 + dj] = sx[(hq + di) * 66 + (wq + dj)];
            }
        float o = 0.f;
#pragma unroll
        for (int kk = 0; kk < 9; kk++) {
            float ks = tb[kk];
#pragma unroll
            for (int r = 0; r < 9; r++)
                ks = fmaf(ywin[r], taps[kk * 9 + r], ks);
            o = fmaf(xwin[kk], ks, o);
        }
        Out[((size_t)b * CH + c) * HWP + pp] = o;
        sum += o;
    }
    red[tid] = sum;
    __syncthreads();
    for (int s = 128; s > 0; s >>= 1) {
        if (tid < s) red[tid] += red[tid + s];
        __syncthreads();
    }
    if (tid == 0) Mean[b * CH + c] = red[0] * (1.f / HWP);
}

// ============================================================
// SE gate
// ============================================================
__global__ __launch_bounds__(192) void se_kernel(
    const float* __restrict__ Mean,
    const float* __restrict__ wc0, const float* __restrict__ bc0,
    const float* __restrict__ wc1, const float* __restrict__ bc1,
    float* __restrict__ Gate)
{
    __shared__ float m[CH];
    __shared__ float hbuf[CH];
    int i = threadIdx.x;
    for (int b = 0; b < BSZ; b++) {
        m[i] = Mean[b * CH + i];
        __syncthreads();
        float s = bc0[i];
        const float* w = wc0 + (size_t)i * CH;
#pragma unroll 8
        for (int j = 0; j < CH; j++) s = fmaf(w[j], m[j], s);
        hbuf[i] = s > 0.f ? s : 0.1f * s;
        __syncthreads();
        float s2 = bc1[i];
        const float* w2 = wc1 + (size_t)i * CH;
#pragma unroll 8
        for (int j = 0; j < CH; j++) s2 = fmaf(w2[j], hbuf[j], s2);
        Gate[b * CH + i] = 1.f / (1.f + expf(-s2));
        __syncthreads();
    }
}

extern "C" void kernel_launch(void* const* d_in, const int* in_sizes, int n_in,
                              void* d_out, int out_size)
{
    const float* input = (const float*)d_in[0];
    const float* lc    = (const float*)d_in[1];
    const int*   mask  = (const int*)d_in[2];
    const float* w0  = (const float*)d_in[3];
    const float* b0  = (const float*)d_in[4];
    const float* w1  = (const float*)d_in[5];
    const float* b1  = (const float*)d_in[6];
    const float* ws0 = (const float*)d_in[7];
    const float* bs0 = (const float*)d_in[8];
    const float* ws1 = (const float*)d_in[9];
    const float* bs1 = (const float*)d_in[10];
    const float* ws2 = (const float*)d_in[11];
    const float* bs2 = (const float*)d_in[12];
    const float* wc0 = (const float*)d_in[13];
    const float* bc0 = (const float*)d_in[14];
    const float* wc1 = (const float*)d_in[15];
    const float* bc1 = (const float*)d_in[16];
    const float* wo  = (const float*)d_in[17];
    const float* bo  = (const float*)d_in[18];
    float* out = (float*)d_out;

    float *pb0, *pb1, *pb2, *pb3, *pWr, *pT, *pMean, *pGate;
    cudaGetSymbolAddress((void**)&pb0, g_b0);
    cudaGetSymbolAddress((void**)&pb1, g_b1);
    cudaGetSymbolAddress((void**)&pb2, g_b2);
    cudaGetSymbolAddress((void**)&pb3, g_b3);
    cudaGetSymbolAddress((void**)&pWr, g_wr);
    cudaGetSymbolAddress((void**)&pT, g_T);
    cudaGetSymbolAddress((void**)&pMean, g_mean);
    cudaGetSymbolAddress((void**)&pGate, g_gate);

    static int smem_set = 0;
    const int conv_smem = (9 * 64 * 20 + 16 * 6 * 68) * 4;   // 72192 bytes
    if (!smem_set) {
        cudaFuncSetAttribute(conv3x3_tc,
                             cudaFuncAttributeMaxDynamicSharedMemorySize, conv_smem);
        smem_set = 1;
    }

    dim3 grid(16, 3, 8), blk(256);

    // 0) reorder ws1 for the implicit-GEMM conv
    reorder_w<<<(9 * CH * CH + 255) / 256, 256>>>(ws1, pWr);
    // 1) v = lrelu(conv1x1(input, w0, b0))
    gemm1x1_tc<true, false, false><<<grid, blk>>>(
        input, w0, b0, pb0, 192, nullptr, nullptr, nullptr, nullptr);
    // 2) x = conv1x1(v, w1, b1)
    gemm1x1_tc<false, false, false><<<grid, blk>>>(
        pb0, w1, b1, pb1, 192, nullptr, nullptr, nullptr, nullptr);
    // 3) T table (center-half of ws0 applied to list_center)
    tgen_kernel<<<BSZ * MASKN, 192>>>(lc, ws0, pT);
    // 4) y0 = lrelu(ws0_x * x + T[b,mask] + bs0)
    gemm1x1_tc<true, true, false><<<grid, blk>>>(
        pb1, ws0, bs0, pb2, 384, mask, pT, nullptr, nullptr);
    // 5) y1 = lrelu(conv3x3(y0, ws1, bs1))
    conv3x3_tc<<<grid, blk, conv_smem>>>(pb2, pWr, bs1, pb3);
    // 6) out_feat = dynamic_conv(x, depthwise(y1)) ; per-(b,c) mean
    dyn_kernel<<<dim3(CH, BSZ), 256>>>(pb3, pb1, ws2, bs2, pb0, pMean);
    // 7) gate
    se_kernel<<<1, 192>>>(pMean, wc0, bc0, wc1, bc1, pGate);
    // 8) out = conv1x1(gate*out_feat, wo, bo) + input
    gemm1x1_tc<false, false, true><<<grid, blk>>>(
        pb0, wo, bo, out, 192, nullptr, nullptr, pGate, input);
}

// round 3
// speedup vs baseline: 4.4670x; 1.8816x over previous
#include <cuda_runtime.h>
#include <math.h>
#include <stdint.h>

#define BSZ 8
#define CH 192
#define HWP 4096
#define MASKN 16

// ---- scratch (static device globals; no allocation in kernel_launch) ----
__device__ float g_b0[BSZ * CH * HWP];   // v, then dyn-conv output
__device__ float g_b1[BSZ * CH * HWP];   // x
__device__ float g_b2[BSZ * CH * HWP];   // y0
__device__ float g_b3[BSZ * CH * HWP];   // y1
__device__ float g_wr[9 * CH * CH];      // reordered ws1: [r][co][ci]
__device__ float g_T[BSZ * MASKN * CH];
__device__ float g_mean[BSZ * CH];
__device__ float g_gate[BSZ * CH];

// ---- tf32 mma m16n8k8 (row.col) ----
__device__ __forceinline__ void mma_tf32(float* c, const uint32_t* a, const uint32_t* b)
{
    asm("mma.sync.aligned.m16n8k8.row.col.f32.tf32.tf32.f32 "
        "{%0,%1,%2,%3}, {%4,%5,%6,%7}, {%8,%9}, {%0,%1,%2,%3};\n"
        : "+f"(c[0]), "+f"(c[1]), "+f"(c[2]), "+f"(c[3])
        : "r"(a[0]), "r"(a[1]), "r"(a[2]), "r"(a[3]), "r"(b[0]), "r"(b[1]));
}

#define CP16(dst, src) \
    asm volatile("cp.async.cg.shared.global [%0], [%1], 16;\n" :: "r"(dst), "l"(src))
#define CP_COMMIT() asm volatile("cp.async.commit_group;\n")
#define CP_WAIT0()  asm volatile("cp.async.wait_group 0;\n")

// ============================================================
// 1x1 conv as GEMM, tensor cores, 2-stage cp.async pipeline.
// CTA: BM=64 (co), BN=256 (pixels), BK=16. 8 warps = 2(m) x 4(n).
// FINAL: gate folded into A: (W*diag(g)) @ X.
// ============================================================
template <bool LRELU, bool ADDT, bool FINAL>
__global__ __launch_bounds__(256) void gemm1x1_tc(
    const float* __restrict__ X, const float* __restrict__ W,
    const float* __restrict__ bias, float* __restrict__ Y,
    int wld,
    const int* __restrict__ mask, const float* __restrict__ Tt,
    const float* __restrict__ gate, const float* __restrict__ resid)
{
    __shared__ float As[2][64][20];
    __shared__ float Bs[2][16][264];
    __shared__ float sgate[CH];

    const int b   = blockIdx.z;
    const int m0  = blockIdx.y * 64;
    const int n0  = blockIdx.x * 256;
    const int tid = threadIdx.x;
    const int lane = tid & 31;
    const int warp = tid >> 5;
    const int wm = warp >> 2;        // 0..1
    const int wn = warp & 3;         // 0..3

    const float* Xb = X + (size_t)b * CH * HWP;

    if (FINAL) {
        if (tid < CH) sgate[tid] = gate[b * CH + tid];
    }

    uint32_t s_as = (uint32_t)__cvta_generic_to_shared(&As[0][0][0]);
    uint32_t s_bs = (uint32_t)__cvta_generic_to_shared(&Bs[0][0][0]);

    float c[2][8][4];
#pragma unroll
    for (int i = 0; i < 2; i++)
#pragma unroll
        for (int j = 0; j < 8; j++)
#pragma unroll
            for (int q = 0; q < 4; q++) c[i][j][q] = 0.f;

    auto issue = [&](int kt, int st) {
        uint32_t ab = s_as + st * (1280 * 4);
        {
            int i = tid >> 2, j0 = (tid & 3) * 4;
            CP16(ab + (uint32_t)(i * 20 + j0) * 4,
                 W + (size_t)(m0 + i) * wld + kt + j0);
        }
        uint32_t bb = s_bs + st * (4224 * 4);
#pragma unroll
        for (int t = 0; t < 4; t++) {
            int idx = tid + t * 256;
            int k = idx >> 6, nb = (idx & 63) * 4;
            CP16(bb + (uint32_t)(k * 264 + nb) * 4,
                 Xb + (size_t)(kt + k) * HWP + n0 + nb);
        }
    };

    issue(0, 0);
    CP_COMMIT();

    for (int step = 0; step < 12; step++) {
        CP_WAIT0();
        __syncthreads();
        if (step < 11) { issue((step + 1) * 16, (step + 1) & 1); CP_COMMIT(); }

        const float (*Ac)[20]  = As[step & 1];
        const float (*Bc)[264] = Bs[step & 1];
        const int kt = step * 16;

#pragma unroll
        for (int ks = 0; ks < 2; ks++) {
            const int kk = ks * 8 + (lane & 3);
            float g0 = 1.f, g4 = 1.f;
            if (FINAL) { g0 = sgate[kt + kk]; g4 = sgate[kt + kk + 4]; }
            uint32_t a[2][4];
#pragma unroll
            for (int mt = 0; mt < 2; mt++) {
                int row = wm * 32 + mt * 16 + (lane >> 2);
                float a0 = Ac[row][kk],     a1 = Ac[row + 8][kk];
                float a2 = Ac[row][kk + 4], a3 = Ac[row + 8][kk + 4];
                if (FINAL) { a0 *= g0; a1 *= g0; a2 *= g4; a3 *= g4; }
                a[mt][0] = __float_as_uint(a0);
                a[mt][1] = __float_as_uint(a1);
                a[mt][2] = __float_as_uint(a2);
                a[mt][3] = __float_as_uint(a3);
            }
#pragma unroll
            for (int nt = 0; nt < 8; nt++) {
                int n = wn * 64 + nt * 8 + (lane >> 2);
                uint32_t bf[2];
                bf[0] = __float_as_uint(Bc[kk][n]);
                bf[1] = __float_as_uint(Bc[kk + 4][n]);
                mma_tf32(c[0][nt], a[0], bf);
                mma_tf32(c[1][nt], a[1], bf);
            }
        }
    }

    // epilogue
#pragma unroll
    for (int mt = 0; mt < 2; mt++) {
        int cob = m0 + wm * 32 + mt * 16 + (lane >> 2);
#pragma unroll
        for (int half = 0; half < 2; half++) {
            int co = cob + half * 8;
            float bi = bias[co];
#pragma unroll
            for (int nt = 0; nt < 8; nt++) {
                int p = n0 + wn * 64 + nt * 8 + (lane & 3) * 2;
                float v0 = c[mt][nt][half * 2 + 0] + bi;
                float v1 = c[mt][nt][half * 2 + 1] + bi;
                if (ADDT) {
                    int mk0 = mask[b * HWP + p];
                    int mk1 = mask[b * HWP + p + 1];
                    v0 += Tt[(b * MASKN + mk0) * CH + co];
                    v1 += Tt[(b * MASKN + mk1) * CH + co];
                }
                if (LRELU) {
                    v0 = v0 > 0.f ? v0 : 0.1f * v0;
                    v1 = v1 > 0.f ? v1 : 0.1f * v1;
                }
                if (FINAL) {
                    v0 += resid[((size_t)b * CH + co) * HWP + p];
                    v1 += resid[((size_t)b * CH + co) * HWP + p + 1];
                }
                *(float2*)&Y[((size_t)b * CH + co) * HWP + p] = make_float2(v0, v1);
            }
        }
    }
}

// ============================================================
// 3x3 conv, tensor cores, 2-stage cp.async pipeline.
// CTA: BM=64, BN=512 (8 image rows). 8 warps, warp tile 64x64.
// Halo layout: Ps[k][rr][68], data at col 4..67 (16B-aligned cp.async),
// col 3 = left pad, col 68 aliases next row's never-written col 0 =
// right pad; OOB rows never written -> persistent zeros from memset.
// ============================================================
__global__ __launch_bounds__(256) void conv3x3_tc(
    const float* __restrict__ X, const float* __restrict__ Wr,
    const float* __restrict__ bias, float* __restrict__ Y)
{
    extern __shared__ float smem[];
    float* Asb = smem;                     // [2][9][64][20] = 23040
    float* Psb = smem + 2 * 11520;         // [2][10884]

    const int b    = blockIdx.z;
    const int m0   = blockIdx.y * 64;
    const int tile = blockIdx.x;           // 0..7
    const int row0 = tile * 8;
    const int n0   = tile * 512;
    const int tid  = threadIdx.x;
    const int lane = tid & 31;
    const int wn   = tid >> 5;             // 0..7

    const float* Xb = X + (size_t)b * CH * HWP;

    // zero Ps (both stages + pad) once; OOB rows / pad cols stay zero
    for (int i = tid; i < 2 * 10884; i += 256) Psb[i] = 0.f;
    __syncthreads();

    uint32_t s_as = (uint32_t)__cvta_generic_to_shared(Asb);
    uint32_t s_ps = (uint32_t)__cvta_generic_to_shared(Psb);

    float c[4][8][4];
#pragma unroll
    for (int i = 0; i < 4; i++)
#pragma unroll
        for (int j = 0; j < 8; j++)
#pragma unroll
            for (int q = 0; q < 4; q++) c[i][j][q] = 0.f;

    auto issue = [&](int kt, int st) {
        uint32_t ab = s_as + st * (11520 * 4);
#pragma unroll
        for (int t = 0; t < 9; t++) {
            int idx = tid + t * 256;
            int r = idx >> 8;
            int rem = idx & 255;
            int i = rem >> 2, j0 = (rem & 3) * 4;
            CP16(ab + (uint32_t)((r * 64 + i) * 20 + j0) * 4,
                 Wr + ((size_t)r * CH + m0 + i) * CH + kt + j0);
        }
        uint32_t pb = s_ps + st * (10884 * 4);
#pragma unroll
        for (int t = 0; t < 10; t++) {
            int idx = tid + t * 256;
            int k = idx / 160;
            int rem = idx - k * 160;
            int rr = rem >> 4;
            int q  = rem & 15;
            int hh = row0 + rr - 1;
            if (hh >= 0 && hh < 64) {
                CP16(pb + (uint32_t)((k * 10 + rr) * 68 + 4 + q * 4) * 4,
                     Xb + (size_t)(kt + k) * HWP + hh * 64 + q * 4);
            }
        }
    };

    issue(0, 0);
    CP_COMMIT();

    for (int step = 0; step < 12; step++) {
        CP_WAIT0();
        __syncthreads();
        if (step < 11) { issue((step + 1) * 16, (step + 1) & 1); CP_COMMIT(); }

        const float* Ac = Asb + (step & 1) * 11520;
        const float* Pc = Psb + (step & 1) * 10884;

#pragma unroll 1
        for (int r = 0; r < 9; r++) {
            const int di = r / 3, dj = r - (r / 3) * 3;
            const float* Ar = Ac + r * 1280;
#pragma unroll
            for (int ks = 0; ks < 2; ks++) {
                const int kk = ks * 8 + (lane & 3);
                uint32_t a[4][4];
#pragma unroll
                for (int mt = 0; mt < 4; mt++) {
                    int rowm = mt * 16 + (lane >> 2);
                    a[mt][0] = __float_as_uint(Ar[rowm * 20 + kk]);
                    a[mt][1] = __float_as_uint(Ar[(rowm + 8) * 20 + kk]);
                    a[mt][2] = __float_as_uint(Ar[rowm * 20 + kk + 4]);
                    a[mt][3] = __float_as_uint(Ar[(rowm + 8) * 20 + kk + 4]);
                }
#pragma unroll
                for (int nt = 0; nt < 8; nt++) {
                    int n = wn * 64 + nt * 8 + (lane >> 2);
                    int prow = (n >> 6) + di;
                    int pcol = (n & 63) + dj + 3;
                    uint32_t bf[2];
                    bf[0] = __float_as_uint(Pc[(kk * 10 + prow) * 68 + pcol]);
                    bf[1] = __float_as_uint(Pc[((kk + 4) * 10 + prow) * 68 + pcol]);
#pragma unroll
                    for (int mt = 0; mt < 4; mt++)
                        mma_tf32(c[mt][nt], a[mt], bf);
                }
            }
        }
    }

    // epilogue: bias + lrelu
#pragma unroll
    for (int mt = 0; mt < 4; mt++) {
#pragma unroll
        for (int half = 0; half < 2; half++) {
            int co = m0 + mt * 16 + (lane >> 2) + half * 8;
            float bi = bias[co];
#pragma unroll
            for (int nt = 0; nt < 8; nt++) {
                int p = n0 + wn * 64 + nt * 8 + (lane & 3) * 2;
                float v0 = c[mt][nt][half * 2 + 0] + bi;
                float v1 = c[mt][nt][half * 2 + 1] + bi;
                v0 = v0 > 0.f ? v0 : 0.1f * v0;
                v1 = v1 > 0.f ? v1 : 0.1f * v1;
                *(float2*)&Y[((size_t)b * CH + co) * HWP + p] = make_float2(v0, v1);
            }
        }
    }
}

// ============================================================
// Reorder ws1[co][ci][r] -> Wr[r][co][ci]
// ============================================================
__global__ void reorder_w(const float* __restrict__ ws1, float* __restrict__ wr)
{
    int idx = blockIdx.x * 256 + threadIdx.x;
    if (idx < 9 * CH * CH) {
        int ci = idx % CH;
        int co = (idx / CH) % CH;
        int r  = idx / (CH * CH);
        wr[idx] = ws1[(co * CH + ci) * 9 + r];
    }
}

// ============================================================
// T[b,m,co] = sum_ci ws0[co, 192+ci] * list_center[b,m,ci]
// warp-per-co, lanes split ci, shfl reduce.
// ============================================================
__global__ __launch_bounds__(256) void tgen_kernel(
    const float* __restrict__ lc, const float* __restrict__ ws0,
    float* __restrict__ T)
{
    __shared__ float cvec[CH];
    const int bm = blockIdx.x;
    const int tid = threadIdx.x;
    if (tid < CH) cvec[tid] = lc[(size_t)bm * CH + tid];
    __syncthreads();
    const int warp = tid >> 5, lane = tid & 31;
    for (int co = warp; co < CH; co += 8) {
        const float* w = ws0 + (size_t)co * (2 * CH) + CH;
        float s = 0.f;
#pragma unroll
        for (int j = lane; j < CH; j += 32) s = fmaf(w[j], cvec[j], s);
#pragma unroll
        for (int o = 16; o; o >>= 1) s += __shfl_xor_sync(0xffffffffu, s, o);
        if (lane == 0) T[bm * CH + co] = s;
    }
}

// ============================================================
// Fused depthwise-3x3 (k_sp) + dynamic conv + mean reduce.
// ============================================================
__global__ __launch_bounds__(256) void dyn_kernel(
    const float* __restrict__ Y1, const float* __restrict__ Xf,
    const float* __restrict__ ws2, const float* __restrict__ bs2,
    float* __restrict__ Out, float* __restrict__ Mean)
{
    __shared__ float sy[66 * 66];
    __shared__ float sx[66 * 66];
    __shared__ float taps[81];
    __shared__ float tb[9];
    __shared__ float red[256];

    const int c = blockIdx.x;
    const int b = blockIdx.y;
    const int tid = threadIdx.x;

    const float* y1p = Y1 + ((size_t)b * CH + c) * HWP;
    const float* xp  = Xf + ((size_t)b * CH + c) * HWP;

    for (int idx = tid; idx < 66 * 66; idx += 256) {
        int hh = idx / 66 - 1;
        int ww = idx % 66 - 1;
        bool ok = (hh >= 0 && hh < 64 && ww >= 0 && ww < 64);
        sy[idx] = ok ? y1p[hh * 64 + ww] : 0.f;
        sx[idx] = ok ? xp[hh * 64 + ww] : 0.f;
    }
    if (tid < 81) taps[tid] = ws2[c * 81 + tid];
    if (tid < 9)  tb[tid]   = bs2[c * 9 + tid];
    __syncthreads();

    float sum = 0.f;
    for (int pp = tid; pp < HWP; pp += 256) {
        int hq = pp >> 6;
        int wq = pp & 63;
        float ywin[9], xwin[9];
#pragma unroll
        for (int di = 0; di < 3; di++)
#pragma unroll
            for (int dj = 0; dj < 3; dj++) {
                ywin[di * 3 + dj] = sy[(hq + di) * 66 + (wq + dj)];
                xwin[di * 3 + dj] = sx[(hq + di) * 66 + (wq + dj)];
            }
        float o = 0.f;
#pragma unroll
        for (int kk = 0; kk < 9; kk++) {
            float ks = tb[kk];
#pragma unroll
            for (int r = 0; r < 9; r++)
                ks = fmaf(ywin[r], taps[kk * 9 + r], ks);
            o = fmaf(xwin[kk], ks, o);
        }
        Out[((size_t)b * CH + c) * HWP + pp] = o;
        sum += o;
    }
    red[tid] = sum;
    __syncthreads();
    for (int s = 128; s > 0; s >>= 1) {
        if (tid < s) red[tid] += red[tid + s];
        __syncthreads();
    }
    if (tid == 0) Mean[b * CH + c] = red[0] * (1.f / HWP);
}

// ============================================================
// SE gate (one block per batch element)
// ============================================================
__global__ __launch_bounds__(192) void se_kernel(
    const float* __restrict__ Mean,
    const float* __restrict__ wc0, const float* __restrict__ bc0,
    const float* __restrict__ wc1, const float* __restrict__ bc1,
    float* __restrict__ Gate)
{
    __shared__ float m[CH];
    __shared__ float hbuf[CH];
    const int b = blockIdx.x;
    const int i = threadIdx.x;
    m[i] = Mean[b * CH + i];
    __syncthreads();
    float s = bc0[i];
    const float* w = wc0 + (size_t)i * CH;
#pragma unroll 8
    for (int j = 0; j < CH; j++) s = fmaf(w[j], m[j], s);
    hbuf[i] = s > 0.f ? s : 0.1f * s;
    __syncthreads();
    float s2 = bc1[i];
    const float* w2 = wc1 + (size_t)i * CH;
#pragma unroll 8
    for (int j = 0; j < CH; j++) s2 = fmaf(w2[j], hbuf[j], s2);
    Gate[b * CH + i] = 1.f / (1.f + expf(-s2));
}

extern "C" void kernel_launch(void* const* d_in, const int* in_sizes, int n_in,
                              void* d_out, int out_size)
{
    const float* input = (const float*)d_in[0];
    const float* lc    = (const float*)d_in[1];
    const int*   mask  = (const int*)d_in[2];
    const float* w0  = (const float*)d_in[3];
    const float* b0  = (const float*)d_in[4];
    const float* w1  = (const float*)d_in[5];
    const float* b1  = (const float*)d_in[6];
    const float* ws0 = (const float*)d_in[7];
    const float* bs0 = (const float*)d_in[8];
    const float* ws1 = (const float*)d_in[9];
    const float* bs1 = (const float*)d_in[10];
    const float* ws2 = (const float*)d_in[11];
    const float* bs2 = (const float*)d_in[12];
    const float* wc0 = (const float*)d_in[13];
    const float* bc0 = (const float*)d_in[14];
    const float* wc1 = (const float*)d_in[15];
    const float* bc1 = (const float*)d_in[16];
    const float* wo  = (const float*)d_in[17];
    const float* bo  = (const float*)d_in[18];
    float* out = (float*)d_out;

    float *pb0, *pb1, *pb2, *pb3, *pWr, *pT, *pMean, *pGate;
    cudaGetSymbolAddress((void**)&pb0, g_b0);
    cudaGetSymbolAddress((void**)&pb1, g_b1);
    cudaGetSymbolAddress((void**)&pb2, g_b2);
    cudaGetSymbolAddress((void**)&pb3, g_b3);
    cudaGetSymbolAddress((void**)&pWr, g_wr);
    cudaGetSymbolAddress((void**)&pT, g_T);
    cudaGetSymbolAddress((void**)&pMean, g_mean);
    cudaGetSymbolAddress((void**)&pGate, g_gate);

    static int smem_set = 0;
    const int conv_smem = (2 * 11520 + 2 * 10884) * 4;   // 179232 bytes
    if (!smem_set) {
        cudaFuncSetAttribute(conv3x3_tc,
                             cudaFuncAttributeMaxDynamicSharedMemorySize, conv_smem);
        smem_set = 1;
    }

    dim3 grid(16, 3, 8), blk(256);
    dim3 cgrid(8, 3, 8);

    // 0) reorder ws1 for the implicit-GEMM conv
    reorder_w<<<(9 * CH * CH + 255) / 256, 256>>>(ws1, pWr);
    // 1) v = lrelu(conv1x1(input, w0, b0))
    gemm1x1_tc<true, false, false><<<grid, blk>>>(
        input, w0, b0, pb0, 192, nullptr, nullptr, nullptr, nullptr);
    // 2) x = conv1x1(v, w1, b1)
    gemm1x1_tc<false, false, false><<<grid, blk>>>(
        pb0, w1, b1, pb1, 192, nullptr, nullptr, nullptr, nullptr);
    // 3) T table (center-half of ws0 applied to list_center)
    tgen_kernel<<<BSZ * MASKN, 256>>>(lc, ws0, pT);
    // 4) y0 = lrelu(ws0_x * x + T[b,mask] + bs0)
    gemm1x1_tc<true, true, false><<<grid, blk>>>(
        pb1, ws0, bs0, pb2, 384, mask, pT, nullptr, nullptr);
    // 5) y1 = lrelu(conv3x3(y0, ws1, bs1))
    conv3x3_tc<<<cgrid, blk, conv_smem>>>(pb2, pWr, bs1, pb3);
    // 6) out_feat = dynamic_conv(x, depthwise(y1)) ; per-(b,c) mean
    dyn_kernel<<<dim3(CH, BSZ), 256>>>(pb3, pb1, ws2, bs2, pb0, pMean);
    // 7) gate
    se_kernel<<<BSZ, 192>>>(pMean, wc0, bc0, wc1, bc1, pGate);
    // 8) out = conv1x1(gate*out_feat, wo, bo) + input
    gemm1x1_tc<false, false, true><<<grid, blk>>>(
        pb0, wo, bo, out, 192, nullptr, nullptr, pGate, input);
}

// round 5
// speedup vs baseline: 5.7241x; 1.2814x over previous
#include <cuda_runtime.h>
#include <cuda_bf16.h>
#include <math.h>
#include <stdint.h>

#define BSZ 8
#define CH 192
#define HWP 4096
#define MASKN 16

typedef __nv_bfloat16 bf16;

// ---- scratch (static device globals) ----
__device__ bf16 g_x0[BSZ * CH * HWP];    // input converted to bf16
__device__ bf16 g_b0[BSZ * CH * HWP];    // v, then dyn-conv output
__device__ bf16 g_b1[BSZ * CH * HWP];    // x
__device__ bf16 g_b2[BSZ * CH * HWP];    // y0
__device__ bf16 g_b3[BSZ * CH * HWP];    // y1
__device__ bf16 g_w0b[CH * CH];
__device__ bf16 g_w1b[CH * CH];
__device__ bf16 g_wsxb[CH * CH];         // x-half of ws0
__device__ bf16 g_wob[CH * CH];
__device__ bf16 g_wrb[9 * CH * CH];      // reordered ws1: [r][co][ci]
__device__ float g_T[BSZ * MASKN * CH];
__device__ float g_mean[BSZ * CH];
__device__ float g_gate[BSZ * CH];

// ---- bf16 mma m16n8k16 (row.col), fp32 accumulate ----
__device__ __forceinline__ void mma_bf16(float* c, const uint32_t* a, uint32_t b0, uint32_t b1)
{
    asm("mma.sync.aligned.m16n8k16.row.col.f32.bf16.bf16.f32 "
        "{%0,%1,%2,%3}, {%4,%5,%6,%7}, {%8,%9}, {%0,%1,%2,%3};\n"
        : "+f"(c[0]), "+f"(c[1]), "+f"(c[2]), "+f"(c[3])
        : "r"(a[0]), "r"(a[1]), "r"(a[2]), "r"(a[3]), "r"(b0), "r"(b1));
}

#define LDMX2T(b0, b1, addr) \
    asm volatile("ldmatrix.sync.aligned.m8n8.x2.trans.shared.b16 {%0,%1}, [%2];\n" \
                 : "=r"(b0), "=r"(b1) : "r"(addr))

#define CP16(dst, src) \
    asm volatile("cp.async.cg.shared.global [%0], [%1], 16;\n" :: "r"(dst), "l"(src))
#define CP_COMMIT() asm volatile("cp.async.commit_group;\n")
#define CP_WAIT0()  asm volatile("cp.async.wait_group 0;\n")

__device__ __forceinline__ uint32_t pkbf(const bf16& lo, const bf16& hi)
{
    return (uint32_t)(*(const uint16_t*)&lo) | ((uint32_t)(*(const uint16_t*)&hi) << 16);
}

// ============================================================
// 1x1 conv as GEMM, bf16 tensor cores, 2-stage cp.async pipeline.
// CTA: BM=64 (co), BN=256 (pixels), BK=16. 8 warps = 2(m) x 4(n).
// A = weights [co][ci] bf16, B = activations [ci][pix] bf16 (ldmatrix.trans).
// FINAL: gate folded into A at staging; fp32 output + residual.
// ============================================================
template <bool LRELU, bool ADDT, bool FINAL>
__global__ __launch_bounds__(256) void gemm1x1_tc(
    const bf16* __restrict__ X, const bf16* __restrict__ Wb,
    const float* __restrict__ bias, void* __restrict__ Yv,
    const int* __restrict__ mask, const float* __restrict__ Tt,
    const float* __restrict__ gate, const float* __restrict__ resid)
{
    __shared__ __align__(16) bf16 As[2][64][24];   // row = 48B (16-mult)
    __shared__ __align__(16) bf16 Bs[2][16][264];  // row = 528B (16-mult)
    __shared__ float sgate[CH];

    const int b   = blockIdx.z;
    const int m0  = blockIdx.y * 64;
    const int n0  = blockIdx.x * 256;
    const int tid = threadIdx.x;
    const int lane = tid & 31;
    const int warp = tid >> 5;
    const int wm = warp >> 2;        // 0..1
    const int wn = warp & 3;         // 0..3
    const int tq = lane & 3;         // thread-in-group
    const int gq = lane >> 2;        // group

    const bf16* Xb = X + (size_t)b * CH * HWP;

    if (FINAL) {
        if (tid < CH) sgate[tid] = gate[b * CH + tid];
        __syncthreads();
    }

    uint32_t s_as = (uint32_t)__cvta_generic_to_shared(&As[0][0][0]);
    uint32_t s_bs = (uint32_t)__cvta_generic_to_shared(&Bs[0][0][0]);

    float c[2][8][4];
#pragma unroll
    for (int i = 0; i < 2; i++)
#pragma unroll
        for (int j = 0; j < 8; j++)
#pragma unroll
            for (int q = 0; q < 4; q++) c[i][j][q] = 0.f;

    auto issue = [&](int kt, int st) {
        if (FINAL) {
            // gate-folded A staged manually (bf16 * fp32 gate -> bf16)
            if (tid < 128) {
                int co = tid >> 1, h8 = (tid & 1) * 8;
                const bf16* src = Wb + (size_t)(m0 + co) * CH + kt + h8;
                bf16 tmp[8];
                *(uint4*)tmp = *(const uint4*)src;
                bf16 dst8[8];
#pragma unroll
                for (int i = 0; i < 8; i++)
                    dst8[i] = __float2bfloat16(__bfloat162float(tmp[i]) * sgate[kt + h8 + i]);
                *(uint4*)&As[st][co][h8] = *(uint4*)dst8;
            }
        } else {
            if (tid < 128) {
                int co = tid >> 1, h8 = (tid & 1) * 8;
                CP16(s_as + (uint32_t)(st * 1536 + co * 24 + h8) * 2,
                     Wb + (size_t)(m0 + co) * CH + kt + h8);
            }
        }
#pragma unroll
        for (int t = 0; t < 2; t++) {
            int idx = tid + t * 256;
            int k = idx >> 5, q = idx & 31;
            CP16(s_bs + (uint32_t)(st * 4224 + k * 264 + q * 8) * 2,
                 Xb + (size_t)(kt + k) * HWP + n0 + q * 8);
        }
    };

    issue(0, 0);
    CP_COMMIT();

    for (int step = 0; step < 12; step++) {
        CP_WAIT0();
        __syncthreads();
        if (step < 11) { issue((step + 1) * 16, (step + 1) & 1); CP_COMMIT(); }

        const bf16* Ac = &As[step & 1][0][0];
        uint32_t sBc = s_bs + (step & 1) * 4224 * 2;

        uint32_t a[2][4];
#pragma unroll
        for (int mt = 0; mt < 2; mt++) {
            int row = wm * 32 + mt * 16 + gq;
            const bf16* r0 = Ac + row * 24;
            const bf16* r1 = Ac + (row + 8) * 24;
            a[mt][0] = *(const uint32_t*)(r0 + 2 * tq);
            a[mt][1] = *(const uint32_t*)(r1 + 2 * tq);
            a[mt][2] = *(const uint32_t*)(r0 + 2 * tq + 8);
            a[mt][3] = *(const uint32_t*)(r1 + 2 * tq + 8);
        }
        uint32_t badr = sBc + (uint32_t)((lane & 15) * 264 + wn * 64) * 2;
#pragma unroll
        for (int nt = 0; nt < 8; nt++) {
            uint32_t b0, b1;
            LDMX2T(b0, b1, badr + nt * 16);
            mma_bf16(c[0][nt], a[0], b0, b1);
            mma_bf16(c[1][nt], a[1], b0, b1);
        }
    }

    // epilogue
#pragma unroll
    for (int mt = 0; mt < 2; mt++) {
        int cob = m0 + wm * 32 + mt * 16 + gq;
#pragma unroll
        for (int half = 0; half < 2; half++) {
            int co = cob + half * 8;
            float bi = bias[co];
#pragma unroll
            for (int nt = 0; nt < 8; nt++) {
                int p = n0 + wn * 64 + nt * 8 + tq * 2;
                float v0 = c[mt][nt][half * 2 + 0] + bi;
                float v1 = c[mt][nt][half * 2 + 1] + bi;
                if (ADDT) {
                    int mk0 = mask[b * HWP + p];
                    int mk1 = mask[b * HWP + p + 1];
                    v0 += Tt[(b * MASKN + mk0) * CH + co];
                    v1 += Tt[(b * MASKN + mk1) * CH + co];
                }
                if (LRELU) {
                    v0 = v0 > 0.f ? v0 : 0.1f * v0;
                    v1 = v1 > 0.f ? v1 : 0.1f * v1;
                }
                size_t off = ((size_t)b * CH + co) * HWP + p;
                if (FINAL) {
                    v0 += resid[off];
                    v1 += resid[off + 1];
                    *(float2*)((float*)Yv + off) = make_float2(v0, v1);
                } else {
                    __nv_bfloat162 o;
                    o.x = __float2bfloat16(v0);
                    o.y = __float2bfloat16(v1);
                    *(__nv_bfloat162*)((bf16*)Yv + off) = o;
                }
            }
        }
    }
}

// ============================================================
// 3x3 conv, bf16 tensor cores, 2-stage cp.async pipeline.
// CTA: BM=64, BN=512 (8 image rows). 8 warps, warp tile 64x64.
// Patch: [16][10 rows][stride 72] halves, plane stride 728 halves
// (1456 B = 16-mult; shifts 12 banks/plane), data at cols 8..71;
// cols 0..7 + plane tail stay zero (memset once).
// col 72 aliases next row's col 0 (zero) => free right pad.
// ============================================================
#define PST 728
#define PSTAGE (16 * PST)        // 11648 halves per stage
__global__ __launch_bounds__(256) void conv3x3_tc(
    const bf16* __restrict__ X, const bf16* __restrict__ Wr,
    const float* __restrict__ bias, bf16* __restrict__ Y)
{
    extern __shared__ __align__(16) bf16 smem[];
    bf16* Asb = smem;                      // [2][9][64][24] = 27648 halves
    bf16* Psb = smem + 2 * 13824;          // [2][PSTAGE]

    const int b    = blockIdx.z;
    const int m0   = blockIdx.y * 64;
    const int tile = blockIdx.x;           // 0..7
    const int row0 = tile * 8;
    const int n0   = tile * 512;
    const int tid  = threadIdx.x;
    const int lane = tid & 31;
    const int wn   = tid >> 5;             // 0..7
    const int tq = lane & 3;
    const int gq = lane >> 2;

    const bf16* Xb = X + (size_t)b * CH * HWP;

    // zero patch (both stages incl. pads) once
    for (int i = tid; i < PSTAGE; i += 256) ((uint32_t*)Psb)[i] = 0u;
    __syncthreads();

    uint32_t s_as = (uint32_t)__cvta_generic_to_shared(Asb);
    uint32_t s_ps = (uint32_t)__cvta_generic_to_shared(Psb);

    float c[4][8][4];
#pragma unroll
    for (int i = 0; i < 4; i++)
#pragma unroll
        for (int j = 0; j < 8; j++)
#pragma unroll
            for (int q = 0; q < 4; q++) c[i][j][q] = 0.f;

    auto issue = [&](int kt, int st) {
        uint32_t ab = s_as + st * (13824 * 2);
#pragma unroll
        for (int t = 0; t < 5; t++) {      // 9*64*2 = 1152 chunks
            int idx = tid + t * 256;
            if (idx < 1152) {
                int r = idx >> 7;
                int rem = idx & 127;
                int co = rem >> 1, h8 = (rem & 1) * 8;
                CP16(ab + (uint32_t)((r * 64 + co) * 24 + h8) * 2,
                     Wr + ((size_t)r * CH + m0 + co) * CH + kt + h8);
            }
        }
        uint32_t pb = s_ps + st * (PSTAGE * 2);
#pragma unroll
        for (int t = 0; t < 5; t++) {      // 16*10*8 = 1280 chunks
            int idx = tid + t * 256;
            int k = idx / 80;
            int rem = idx - k * 80;
            int rr = rem >> 3;
            int q  = rem & 7;
            int hh = row0 + rr - 1;
            if (hh >= 0 && hh < 64) {
                CP16(pb + (uint32_t)(k * PST + rr * 72 + 8 + q * 8) * 2,
                     Xb + (size_t)(kt + k) * HWP + hh * 64 + q * 8);
            }
        }
    };

    issue(0, 0);
    CP_COMMIT();

    for (int step = 0; step < 12; step++) {
        CP_WAIT0();
        __syncthreads();
        if (step < 11) { issue((step + 1) * 16, (step + 1) & 1); CP_COMMIT(); }

        const bf16* Ac = Asb + (step & 1) * 13824;
        const bf16* Pc = Psb + (step & 1) * PSTAGE;

#pragma unroll 1
        for (int r = 0; r < 9; r++) {
            const int di = r / 3, dj = r - (r / 3) * 3;
            const bf16* Ar = Ac + r * 1536;

            uint32_t a[4][4];
#pragma unroll
            for (int mt = 0; mt < 4; mt++) {
                int rowm = mt * 16 + gq;
                const bf16* r0 = Ar + rowm * 24;
                const bf16* r1 = Ar + (rowm + 8) * 24;
                a[mt][0] = *(const uint32_t*)(r0 + 2 * tq);
                a[mt][1] = *(const uint32_t*)(r1 + 2 * tq);
                a[mt][2] = *(const uint32_t*)(r0 + 2 * tq + 8);
                a[mt][3] = *(const uint32_t*)(r1 + 2 * tq + 8);
            }
#pragma unroll
            for (int nt = 0; nt < 8; nt++) {
                int n = wn * 64 + nt * 8 + gq;
                int prow = (n >> 6) + di;
                int pcol = (n & 63) + dj + 7;
                const bf16* pb0 = Pc + (2 * tq) * PST + prow * 72 + pcol;
                uint32_t b0 = pkbf(pb0[0], pb0[PST]);
                uint32_t b1 = pkbf(pb0[8 * PST], pb0[9 * PST]);
#pragma unroll
                for (int mt = 0; mt < 4; mt++)
                    mma_bf16(c[mt][nt], a[mt], b0, b1);
            }
        }
    }

    // epilogue: bias + lrelu -> bf16
#pragma unroll
    for (int mt = 0; mt < 4; mt++) {
#pragma unroll
        for (int half = 0; half < 2; half++) {
            int co = m0 + mt * 16 + gq + half * 8;
            float bi = bias[co];
#pragma unroll
            for (int nt = 0; nt < 8; nt++) {
                int p = n0 + wn * 64 + nt * 8 + tq * 2;
                float v0 = c[mt][nt][half * 2 + 0] + bi;
                float v1 = c[mt][nt][half * 2 + 1] + bi;
                v0 = v0 > 0.f ? v0 : 0.1f * v0;
                v1 = v1 > 0.f ? v1 : 0.1f * v1;
                __nv_bfloat162 o;
                o.x = __float2bfloat16(v0);
                o.y = __float2bfloat16(v1);
                *(__nv_bfloat162*)&Y[((size_t)b * CH + co) * HWP + p] = o;
            }
        }
    }
}

// ============================================================
// prep: convert weights to bf16 (+ reorder ws1 -> [r][co][ci])
// ============================================================
__global__ void prep_weights(
    const float* __restrict__ w0, const float* __restrict__ w1,
    const float* __restrict__ ws0, const float* __restrict__ ws1,
    const float* __restrict__ wo,
    bf16* __restrict__ w0b, bf16* __restrict__ w1b,
    bf16* __restrict__ wsxb, bf16* __restrict__ wob,
    bf16* __restrict__ wrb)
{
    const int S = CH * CH;
    int idx = blockIdx.x * 256 + threadIdx.x;
    if (idx < S) {
        w0b[idx] = __float2bfloat16(w0[idx]);
    } else if (idx < 2 * S) {
        int i = idx - S;
        w1b[i] = __float2bfloat16(w1[i]);
    } else if (idx < 3 * S) {
        int i = idx - 2 * S;
        int co = i / CH, ci = i % CH;
        wsxb[i] = __float2bfloat16(ws0[(size_t)co * (2 * CH) + ci]);
    } else if (idx < 4 * S) {
        int i = idx - 3 * S;
        wob[i] = __float2bfloat16(wo[i]);
    } else if (idx < 4 * S + 9 * S) {
        int i = idx - 4 * S;
        int ci = i % CH;
        int co = (i / CH) % CH;
        int r  = i / S;
        wrb[i] = __float2bfloat16(ws1[((size_t)co * CH + ci) * 9 + r]);
    }
}

// ============================================================
// prep: convert input fp32 -> bf16 (vectorized)
// ============================================================
__global__ void prep_input(const float4* __restrict__ in, __nv_bfloat162* __restrict__ out, int n4)
{
    int idx = blockIdx.x * 256 + threadIdx.x;
    if (idx < n4) {
        float4 v = in[idx];
        __nv_bfloat162 o0, o1;
        o0.x = __float2bfloat16(v.x); o0.y = __float2bfloat16(v.y);
        o1.x = __float2bfloat16(v.z); o1.y = __float2bfloat16(v.w);
        out[2 * idx]     = o0;
        out[2 * idx + 1] = o1;
    }
}

// ============================================================
// T[b,m,co] = sum_ci ws0[co, 192+ci] * list_center[b,m,ci]
// grid (128 bm, 6 co-groups); warp per 4 co, lanes split ci.
// ============================================================
__global__ __launch_bounds__(256) void tgen_kernel(
    const float* __restrict__ lc, const float* __restrict__ ws0,
    float* __restrict__ T)
{
    __shared__ float cvec[CH];
    const int bm = blockIdx.x;
    const int cg = blockIdx.y;
    const int tid = threadIdx.x;
    if (tid < CH) cvec[tid] = lc[(size_t)bm * CH + tid];
    __syncthreads();
    const int warp = tid >> 5, lane = tid & 31;
    const int co0 = cg * 32 + warp * 4;
#pragma unroll
    for (int q = 0; q < 4; q++) {
        const float* w = ws0 + (size_t)(co0 + q) * (2 * CH) + CH;
        float s = 0.f;
#pragma unroll
        for (int j = lane; j < CH; j += 32) s = fmaf(w[j], cvec[j], s);
#pragma unroll
        for (int o = 16; o; o >>= 1) s += __shfl_xor_sync(0xffffffffu, s, o);
        if (lane == 0) T[bm * CH + co0 + q] = s;
    }
}

// ============================================================
// Fused depthwise-3x3 (k_sp) + dynamic conv + mean reduce. bf16 I/O.
// ============================================================
__global__ __launch_bounds__(256) void dyn_kernel(
    const bf16* __restrict__ Y1, const bf16* __restrict__ Xf,
    const float* __restrict__ ws2, const float* __restrict__ bs2,
    bf16* __restrict__ Out, float* __restrict__ Mean)
{
    __shared__ float sy[66 * 66];
    __shared__ float sx[66 * 66];
    __shared__ float taps[81];
    __shared__ float tb[9];
    __shared__ float red[256];

    const int c = blockIdx.x;
    const int b = blockIdx.y;
    const int tid = threadIdx.x;

    const bf16* y1p = Y1 + ((size_t)b * CH + c) * HWP;
    const bf16* xp  = Xf + ((size_t)b * CH + c) * HWP;

    for (int idx = tid; idx < 66 * 66; idx += 256) {
        int hh = idx / 66 - 1;
        int ww = idx % 66 - 1;
        bool ok = (hh >= 0 && hh < 64 && ww >= 0 && ww < 64);
        sy[idx] = ok ? __bfloat162float(y1p[hh * 64 + ww]) : 0.f;
        sx[idx] = ok ? __bfloat162float(xp[hh * 64 + ww]) : 0.f;
    }
    if (tid < 81) taps[tid] = ws2[c * 81 + tid];
    if (tid < 9)  tb[tid]   = bs2[c * 9 + tid];
    __syncthreads();

    float sum = 0.f;
    for (int pp = tid; pp < HWP; pp += 256) {
        int hq = pp >> 6;
        int wq = pp & 63;
        float ywin[9], xwin[9];
#pragma unroll
        for (int di = 0; di < 3; di++)
#pragma unroll
            for (int dj = 0; dj < 3; dj++) {
                ywin[di * 3 + dj] = sy[(hq + di) * 66 + (wq + dj)];
                xwin[di * 3 + dj] = sx[(hq + di) * 66 + (wq + dj)];
            }
        float o = 0.f;
#pragma unroll
        for (int kk = 0; kk < 9; kk++) {
            float ks = tb[kk];
#pragma unroll
            for (int r = 0; r < 9; r++)
                ks = fmaf(ywin[r], taps[kk * 9 + r], ks);
            o = fmaf(xwin[kk], ks, o);
        }
        Out[((size_t)b * CH + c) * HWP + pp] = __float2bfloat16(o);
        sum += o;
    }
    red[tid] = sum;
    __syncthreads();
    for (int s = 128; s > 0; s >>= 1) {
        if (tid < s) red[tid] += red[tid + s];
        __syncthreads();
    }
    if (tid == 0) Mean[b * CH + c] = red[0] * (1.f / HWP);
}

// ============================================================
// SE gate (one block per batch element)
// ============================================================
__global__ __launch_bounds__(192) void se_kernel(
    const float* __restrict__ Mean,
    const float* __restrict__ wc0, const float* __restrict__ bc0,
    const float* __restrict__ wc1, const float* __restrict__ bc1,
    float* __restrict__ Gate)
{
    __shared__ float m[CH];
    __shared__ float hbuf[CH];
    const int b = blockIdx.x;
    const int i = threadIdx.x;
    m[i] = Mean[b * CH + i];
    __syncthreads();
    float s = bc0[i];
    const float* w = wc0 + (size_t)i * CH;
#pragma unroll 8
    for (int j = 0; j < CH; j++) s = fmaf(w[j], m[j], s);
    hbuf[i] = s > 0.f ? s : 0.1f * s;
    __syncthreads();
    float s2 = bc1[i];
    const float* w2 = wc1 + (size_t)i * CH;
#pragma unroll 8
    for (int j = 0; j < CH; j++) s2 = fmaf(w2[j], hbuf[j], s2);
    Gate[b * CH + i] = 1.f / (1.f + expf(-s2));
}

extern "C" void kernel_launch(void* const* d_in, const int* in_sizes, int n_in,
                              void* d_out, int out_size)
{
    const float* input = (const float*)d_in[0];
    const float* lc    = (const float*)d_in[1];
    const int*   mask  = (const int*)d_in[2];
    const float* w0  = (const float*)d_in[3];
    const float* b0  = (const float*)d_in[4];
    const float* w1  = (const float*)d_in[5];
    const float* b1  = (const float*)d_in[6];
    const float* ws0 = (const float*)d_in[7];
    const float* bs0 = (const float*)d_in[8];
    const float* ws1 = (const float*)d_in[9];
    const float* bs1 = (const float*)d_in[10];
    const float* ws2 = (const float*)d_in[11];
    const float* bs2 = (const float*)d_in[12];
    const float* wc0 = (const float*)d_in[13];
    const float* bc0 = (const float*)d_in[14];
    const float* wc1 = (const float*)d_in[15];
    const float* bc1 = (const float*)d_in[16];
    const float* wo  = (const float*)d_in[17];
    const float* bo  = (const float*)d_in[18];
    float* out = (float*)d_out;

    bf16 *px0, *pb0, *pb1, *pb2, *pb3, *pw0b, *pw1b, *pwsxb, *pwob, *pwrb;
    float *pT, *pMean, *pGate;
    cudaGetSymbolAddress((void**)&px0, g_x0);
    cudaGetSymbolAddress((void**)&pb0, g_b0);
    cudaGetSymbolAddress((void**)&pb1, g_b1);
    cudaGetSymbolAddress((void**)&pb2, g_b2);
    cudaGetSymbolAddress((void**)&pb3, g_b3);
    cudaGetSymbolAddress((void**)&pw0b, g_w0b);
    cudaGetSymbolAddress((void**)&pw1b, g_w1b);
    cudaGetSymbolAddress((void**)&pwsxb, g_wsxb);
    cudaGetSymbolAddress((void**)&pwob, g_wob);
    cudaGetSymbolAddress((void**)&pwrb, g_wrb);
    cudaGetSymbolAddress((void**)&pT, g_T);
    cudaGetSymbolAddress((void**)&pMean, g_mean);
    cudaGetSymbolAddress((void**)&pGate, g_gate);

    static int smem_set = 0;
    const int conv_smem = (2 * 13824 + 2 * PSTAGE) * 2;   // 101,888 bytes
    if (!smem_set) {
        cudaFuncSetAttribute(conv3x3_tc,
                             cudaFuncAttributeMaxDynamicSharedMemorySize, conv_smem);
        smem_set = 1;
    }

    dim3 grid(16, 3, 8), blk(256);
    dim3 cgrid(8, 3, 8);

    // 0) prep: weight conversion/reorder + input conversion
    prep_weights<<<(13 * CH * CH + 255) / 256, 256>>>(
        w0, w1, ws0, ws1, wo, pw0b, pw1b, pwsxb, pwob, pwrb);
    {
        int n4 = BSZ * CH * HWP / 4;
        prep_input<<<(n4 + 255) / 256, 256>>>((const float4*)input, (__nv_bfloat162*)px0, n4);
    }
    // 1) v = lrelu(conv1x1(input, w0, b0))
    gemm1x1_tc<true, false, false><<<grid, blk>>>(
        px0, pw0b, b0, pb0, nullptr, nullptr, nullptr, nullptr);
    // 2) x = conv1x1(v, w1, b1)
    gemm1x1_tc<false, false, false><<<grid, blk>>>(
        pb0, pw1b, b1, pb1, nullptr, nullptr, nullptr, nullptr);
    // 3) T table (center-half of ws0 applied to list_center)
    tgen_kernel<<<dim3(BSZ * MASKN, 6), 256>>>(lc, ws0, pT);
    // 4) y0 = lrelu(wsx * x + T[b,mask] + bs0)
    gemm1x1_tc<true, true, false><<<grid, blk>>>(
        pb1, pwsxb, bs0, pb2, mask, pT, nullptr, nullptr);
    // 5) y1 = lrelu(conv3x3(y0, ws1, bs1))
    conv3x3_tc<<<cgrid, blk, conv_smem>>>(pb2, pwrb, bs1, pb3);
    // 6) out_feat = dynamic_conv(x, depthwise(y1)) ; per-(b,c) mean
    dyn_kernel<<<dim3(CH, BSZ), 256>>>(pb3, pb1, ws2, bs2, pb0, pMean);
    // 7) gate
    se_kernel<<<BSZ, 192>>>(pMean, wc0, bc0, wc1, bc1, pGate);
    // 8) out = conv1x1(gate*out_feat, wo, bo) + input
    gemm1x1_tc<false, false, true><<<grid, blk>>>(
        pb0, pwob, bo, out, nullptr, nullptr, pGate, input);
}

// round 6
// speedup vs baseline: 6.0471x; 1.0564x over previous
#include <cuda_runtime.h>
#include <cuda_bf16.h>
#include <math.h>
#include <stdint.h>

#define BSZ 8
#define CH 192
#define HWP 4096
#define MASKN 16

typedef __nv_bfloat16 bf16;

// ---- scratch (static device globals) ----
__device__ bf16 g_b0[BSZ * CH * HWP];    // dyn-conv output
__device__ bf16 g_b1[BSZ * CH * HWP];    // x
__device__ bf16 g_b2[BSZ * CH * HWP];    // y0
__device__ bf16 g_b3[BSZ * CH * HWP];    // y1
__device__ bf16 g_w0b[CH * CH];
__device__ bf16 g_w1b[CH * CH];
__device__ bf16 g_wsxb[CH * CH];         // x-half of ws0
__device__ bf16 g_wob[CH * CH];
__device__ bf16 g_wrb[9 * CH * CH];      // reordered ws1: [r][co][ci]
__device__ float g_T[BSZ * MASKN * CH];
__device__ float g_mean[BSZ * CH];
__device__ float g_gate[BSZ * CH];

// ---- bf16 mma m16n8k16 (row.col), fp32 accumulate ----
__device__ __forceinline__ void mma_bf16(float* c, const uint32_t* a, uint32_t b0, uint32_t b1)
{
    asm("mma.sync.aligned.m16n8k16.row.col.f32.bf16.bf16.f32 "
        "{%0,%1,%2,%3}, {%4,%5,%6,%7}, {%8,%9}, {%0,%1,%2,%3};\n"
        : "+f"(c[0]), "+f"(c[1]), "+f"(c[2]), "+f"(c[3])
        : "r"(a[0]), "r"(a[1]), "r"(a[2]), "r"(a[3]), "r"(b0), "r"(b1));
}

#define LDMX2T(b0, b1, addr) \
    asm volatile("ldmatrix.sync.aligned.m8n8.x2.trans.shared.b16 {%0,%1}, [%2];\n" \
                 : "=r"(b0), "=r"(b1) : "r"(addr))

#define CP16(dst, src) \
    asm volatile("cp.async.cg.shared.global [%0], [%1], 16;\n" :: "r"(dst), "l"(src))
#define CP_COMMIT() asm volatile("cp.async.commit_group;\n")
#define CP_WAIT0()  asm volatile("cp.async.wait_group 0;\n")

__device__ __forceinline__ uint32_t pkbf(const bf16& lo, const bf16& hi)
{
    return (uint32_t)(*(const uint16_t*)&lo) | ((uint32_t)(*(const uint16_t*)&hi) << 16);
}

// ============================================================
// Fused chain: v = lrelu(W0@in), x = W1@v, y0 = lrelu(Wsx@x + T + bs0)
// One CTA owns 256 pixels; full 192-ch activation tile stays RESIDENT
// in SMEM (ping-pong buffers). Per phase, per 64-co m-chunk: stream the
// 64x192 weight panel once, then a sync-free K-loop of pure LDSM+MMA.
// grid (16, 1, 8) = 128 CTAs, 256 threads, ~228KB smem.
// ============================================================
#define BST 264            // B row stride in halves (bank-spread, 16B-mult)
#define BBUF (CH * BST)    // 50688 halves per activation buffer
#define AST 200            // A row stride in halves (400B, 16B-mult)

__global__ __launch_bounds__(256) void chain3_tc(
    const float* __restrict__ input,
    const bf16* __restrict__ W0, const bf16* __restrict__ W1,
    const bf16* __restrict__ Wsx,
    const float* __restrict__ bias0, const float* __restrict__ bias1,
    const float* __restrict__ bias2,
    const int* __restrict__ mask, const float* __restrict__ Tt,
    bf16* __restrict__ Xout, bf16* __restrict__ Y0out)
{
    extern __shared__ __align__(16) bf16 sm[];
    bf16* Bbuf0 = sm;              // [192][BST]
    bf16* Bbuf1 = sm + BBUF;       // [192][BST]
    bf16* As    = sm + 2 * BBUF;   // [64][AST]

    const int b   = blockIdx.z;
    const int n0  = blockIdx.x * 256;
    const int tid = threadIdx.x;
    const int lane = tid & 31;
    const int warp = tid >> 5;
    const int wm = warp >> 2;      // 0..1
    const int wn = warp & 3;       // 0..3
    const int tq = lane & 3;
    const int gq = lane >> 2;

    // ---- stage input tile fp32 -> bf16 into Bbuf0 ----
    const float* inb = input + (size_t)b * CH * HWP;
    for (int idx = tid; idx < CH * 128; idx += 256) {
        int ch = idx >> 7, pu = idx & 127;
        float2 v = *(const float2*)(inb + (size_t)ch * HWP + n0 + 2 * pu);
        __nv_bfloat162 o;
        o.x = __float2bfloat16(v.x);
        o.y = __float2bfloat16(v.y);
        *(__nv_bfloat162*)(Bbuf0 + ch * BST + 2 * pu) = o;
    }
    __syncthreads();

    uint32_t s_as = (uint32_t)__cvta_generic_to_shared(As);

#pragma unroll 1
    for (int ph = 0; ph < 3; ph++) {
        const bf16* W = (ph == 0) ? W0 : (ph == 1 ? W1 : Wsx);
        const float* bias = (ph == 0) ? bias0 : (ph == 1 ? bias1 : bias2);
        bf16* Bsrc = (ph == 1) ? Bbuf1 : Bbuf0;
        bf16* Bdst = (ph == 0) ? Bbuf1 : Bbuf0;   // unused for ph==2
        uint32_t s_bsrc = (uint32_t)__cvta_generic_to_shared(Bsrc);

#pragma unroll 1
        for (int mc = 0; mc < 3; mc++) {
            const int m0 = mc * 64;

            // stream weight panel 64x192 (24 chunks/row)
#pragma unroll
            for (int t = 0; t < 6; t++) {
                int idx = tid + t * 256;
                int i = idx / 24, c8 = (idx % 24) * 8;
                CP16(s_as + (uint32_t)(i * AST + c8) * 2,
                     W + (size_t)(m0 + i) * CH + c8);
            }
            CP_COMMIT();
            CP_WAIT0();
            __syncthreads();

            float c[2][8][4];
#pragma unroll
            for (int i = 0; i < 2; i++)
#pragma unroll
                for (int j = 0; j < 8; j++)
#pragma unroll
                    for (int q = 0; q < 4; q++) c[i][j][q] = 0.f;

            // sync-free K loop: A resident in As, B resident in Bsrc
#pragma unroll
            for (int kt = 0; kt < CH; kt += 16) {
                uint32_t a[2][4];
#pragma unroll
                for (int mt = 0; mt < 2; mt++) {
                    int row = wm * 32 + mt * 16 + gq;
                    const bf16* r0 = As + row * AST + kt;
                    const bf16* r1 = As + (row + 8) * AST + kt;
                    a[mt][0] = *(const uint32_t*)(r0 + 2 * tq);
                    a[mt][1] = *(const uint32_t*)(r1 + 2 * tq);
                    a[mt][2] = *(const uint32_t*)(r0 + 2 * tq + 8);
                    a[mt][3] = *(const uint32_t*)(r1 + 2 * tq + 8);
                }
                uint32_t badr = s_bsrc
                    + (uint32_t)((kt + (lane & 15)) * BST + wn * 64) * 2;
#pragma unroll
                for (int nt = 0; nt < 8; nt++) {
                    uint32_t bf0, bf1;
                    LDMX2T(bf0, bf1, badr + nt * 16);
                    mma_bf16(c[0][nt], a[0], bf0, bf1);
                    mma_bf16(c[1][nt], a[1], bf0, bf1);
                }
            }

            // epilogue
#pragma unroll
            for (int mt = 0; mt < 2; mt++) {
#pragma unroll
                for (int half = 0; half < 2; half++) {
                    int co = m0 + wm * 32 + mt * 16 + gq + half * 8;
                    float bi = bias[co];
#pragma unroll
                    for (int nt = 0; nt < 8; nt++) {
                        int ploc = wn * 64 + nt * 8 + tq * 2;
                        float v0 = c[mt][nt][half * 2 + 0] + bi;
                        float v1 = c[mt][nt][half * 2 + 1] + bi;
                        if (ph == 2) {
                            int p = n0 + ploc;
                            int mk0 = mask[b * HWP + p];
                            int mk1 = mask[b * HWP + p + 1];
                            v0 += Tt[(b * MASKN + mk0) * CH + co];
                            v1 += Tt[(b * MASKN + mk1) * CH + co];
                        }
                        if (ph != 1) {
                            v0 = v0 > 0.f ? v0 : 0.1f * v0;
                            v1 = v1 > 0.f ? v1 : 0.1f * v1;
                        }
                        __nv_bfloat162 o;
                        o.x = __float2bfloat16(v0);
                        o.y = __float2bfloat16(v1);
                        if (ph < 2)
                            *(__nv_bfloat162*)(Bdst + co * BST + ploc) = o;
                        if (ph == 1)
                            *(__nv_bfloat162*)(Xout + ((size_t)b * CH + co) * HWP + n0 + ploc) = o;
                        if (ph == 2)
                            *(__nv_bfloat162*)(Y0out + ((size_t)b * CH + co) * HWP + n0 + ploc) = o;
                    }
                }
            }
            __syncthreads();
        }
    }
}

// ============================================================
// 1x1 conv as GEMM (used only for the FINAL gated output conv).
// CTA: BM=64, BN=256, BK=16. Gate folded into A; fp32 out + residual.
// ============================================================
template <bool LRELU, bool ADDT, bool FINAL>
__global__ __launch_bounds__(256) void gemm1x1_tc(
    const bf16* __restrict__ X, const bf16* __restrict__ Wb,
    const float* __restrict__ bias, void* __restrict__ Yv,
    const int* __restrict__ mask, const float* __restrict__ Tt,
    const float* __restrict__ gate, const float* __restrict__ resid)
{
    __shared__ __align__(16) bf16 As[2][64][24];
    __shared__ __align__(16) bf16 Bs[2][16][264];
    __shared__ float sgate[CH];

    const int b   = blockIdx.z;
    const int m0  = blockIdx.y * 64;
    const int n0  = blockIdx.x * 256;
    const int tid = threadIdx.x;
    const int lane = tid & 31;
    const int warp = tid >> 5;
    const int wm = warp >> 2;
    const int wn = warp & 3;
    const int tq = lane & 3;
    const int gq = lane >> 2;

    const bf16* Xb = X + (size_t)b * CH * HWP;

    if (FINAL) {
        if (tid < CH) sgate[tid] = gate[b * CH + tid];
        __syncthreads();
    }

    uint32_t s_as = (uint32_t)__cvta_generic_to_shared(&As[0][0][0]);
    uint32_t s_bs = (uint32_t)__cvta_generic_to_shared(&Bs[0][0][0]);

    float c[2][8][4];
#pragma unroll
    for (int i = 0; i < 2; i++)
#pragma unroll
        for (int j = 0; j < 8; j++)
#pragma unroll
            for (int q = 0; q < 4; q++) c[i][j][q] = 0.f;

    auto issue = [&](int kt, int st) {
        if (FINAL) {
            if (tid < 128) {
                int co = tid >> 1, h8 = (tid & 1) * 8;
                const bf16* src = Wb + (size_t)(m0 + co) * CH + kt + h8;
                bf16 tmp[8];
                *(uint4*)tmp = *(const uint4*)src;
                bf16 dst8[8];
#pragma unroll
                for (int i = 0; i < 8; i++)
                    dst8[i] = __float2bfloat16(__bfloat162float(tmp[i]) * sgate[kt + h8 + i]);
                *(uint4*)&As[st][co][h8] = *(uint4*)dst8;
            }
        } else {
            if (tid < 128) {
                int co = tid >> 1, h8 = (tid & 1) * 8;
                CP16(s_as + (uint32_t)(st * 1536 + co * 24 + h8) * 2,
                     Wb + (size_t)(m0 + co) * CH + kt + h8);
            }
        }
#pragma unroll
        for (int t = 0; t < 2; t++) {
            int idx = tid + t * 256;
            int k = idx >> 5, q = idx & 31;
            CP16(s_bs + (uint32_t)(st * 4224 + k * 264 + q * 8) * 2,
                 Xb + (size_t)(kt + k) * HWP + n0 + q * 8);
        }
    };

    issue(0, 0);
    CP_COMMIT();

    for (int step = 0; step < 12; step++) {
        CP_WAIT0();
        __syncthreads();
        if (step < 11) { issue((step + 1) * 16, (step + 1) & 1); CP_COMMIT(); }

        const bf16* Ac = &As[step & 1][0][0];
        uint32_t sBc = s_bs + (step & 1) * 4224 * 2;

        uint32_t a[2][4];
#pragma unroll
        for (int mt = 0; mt < 2; mt++) {
            int row = wm * 32 + mt * 16 + gq;
            const bf16* r0 = Ac + row * 24;
            const bf16* r1 = Ac + (row + 8) * 24;
            a[mt][0] = *(const uint32_t*)(r0 + 2 * tq);
            a[mt][1] = *(const uint32_t*)(r1 + 2 * tq);
            a[mt][2] = *(const uint32_t*)(r0 + 2 * tq + 8);
            a[mt][3] = *(const uint32_t*)(r1 + 2 * tq + 8);
        }
        uint32_t badr = sBc + (uint32_t)((lane & 15) * 264 + wn * 64) * 2;
#pragma unroll
        for (int nt = 0; nt < 8; nt++) {
            uint32_t b0, b1;
            LDMX2T(b0, b1, badr + nt * 16);
            mma_bf16(c[0][nt], a[0], b0, b1);
            mma_bf16(c[1][nt], a[1], b0, b1);
        }
    }

#pragma unroll
    for (int mt = 0; mt < 2; mt++) {
        int cob = m0 + wm * 32 + mt * 16 + gq;
#pragma unroll
        for (int half = 0; half < 2; half++) {
            int co = cob + half * 8;
            float bi = bias[co];
#pragma unroll
            for (int nt = 0; nt < 8; nt++) {
                int p = n0 + wn * 64 + nt * 8 + tq * 2;
                float v0 = c[mt][nt][half * 2 + 0] + bi;
                float v1 = c[mt][nt][half * 2 + 1] + bi;
                if (ADDT) {
                    int mk0 = mask[b * HWP + p];
                    int mk1 = mask[b * HWP + p + 1];
                    v0 += Tt[(b * MASKN + mk0) * CH + co];
                    v1 += Tt[(b * MASKN + mk1) * CH + co];
                }
                if (LRELU) {
                    v0 = v0 > 0.f ? v0 : 0.1f * v0;
                    v1 = v1 > 0.f ? v1 : 0.1f * v1;
                }
                size_t off = ((size_t)b * CH + co) * HWP + p;
                if (FINAL) {
                    v0 += resid[off];
                    v1 += resid[off + 1];
                    *(float2*)((float*)Yv + off) = make_float2(v0, v1);
                } else {
                    __nv_bfloat162 o;
                    o.x = __float2bfloat16(v0);
                    o.y = __float2bfloat16(v1);
                    *(__nv_bfloat162*)((bf16*)Yv + off) = o;
                }
            }
        }
    }
}

// ============================================================
// 3x3 conv, bf16 tensor cores, 2-stage cp.async pipeline. (unchanged R5)
// ============================================================
#define PST 728
#define PSTAGE (16 * PST)
__global__ __launch_bounds__(256) void conv3x3_tc(
    const bf16* __restrict__ X, const bf16* __restrict__ Wr,
    const float* __restrict__ bias, bf16* __restrict__ Y)
{
    extern __shared__ __align__(16) bf16 smem[];
    bf16* Asb = smem;                      // [2][9][64][24]
    bf16* Psb = smem + 2 * 13824;          // [2][PSTAGE]

    const int b    = blockIdx.z;
    const int m0   = blockIdx.y * 64;
    const int tile = blockIdx.x;
    const int row0 = tile * 8;
    const int n0   = tile * 512;
    const int tid  = threadIdx.x;
    const int lane = tid & 31;
    const int wn   = tid >> 5;
    const int tq = lane & 3;
    const int gq = lane >> 2;

    const bf16* Xb = X + (size_t)b * CH * HWP;

    for (int i = tid; i < PSTAGE; i += 256) ((uint32_t*)Psb)[i] = 0u;
    __syncthreads();

    uint32_t s_as = (uint32_t)__cvta_generic_to_shared(Asb);
    uint32_t s_ps = (uint32_t)__cvta_generic_to_shared(Psb);

    float c[4][8][4];
#pragma unroll
    for (int i = 0; i < 4; i++)
#pragma unroll
        for (int j = 0; j < 8; j++)
#pragma unroll
            for (int q = 0; q < 4; q++) c[i][j][q] = 0.f;

    auto issue = [&](int kt, int st) {
        uint32_t ab = s_as + st * (13824 * 2);
#pragma unroll
        for (int t = 0; t < 5; t++) {
            int idx = tid + t * 256;
            if (idx < 1152) {
                int r = idx >> 7;
                int rem = idx & 127;
                int co = rem >> 1, h8 = (rem & 1) * 8;
                CP16(ab + (uint32_t)((r * 64 + co) * 24 + h8) * 2,
                     Wr + ((size_t)r * CH + m0 + co) * CH + kt + h8);
            }
        }
        uint32_t pb = s_ps + st * (PSTAGE * 2);
#pragma unroll
        for (int t = 0; t < 5; t++) {
            int idx = tid + t * 256;
            int k = idx / 80;
            int rem = idx - k * 80;
            int rr = rem >> 3;
            int q  = rem & 7;
            int hh = row0 + rr - 1;
            if (hh >= 0 && hh < 64) {
                CP16(pb + (uint32_t)(k * PST + rr * 72 + 8 + q * 8) * 2,
                     Xb + (size_t)(kt + k) * HWP + hh * 64 + q * 8);
            }
        }
    };

    issue(0, 0);
    CP_COMMIT();

    for (int step = 0; step < 12; step++) {
        CP_WAIT0();
        __syncthreads();
        if (step < 11) { issue((step + 1) * 16, (step + 1) & 1); CP_COMMIT(); }

        const bf16* Ac = Asb + (step & 1) * 13824;
        const bf16* Pc = Psb + (step & 1) * PSTAGE;

#pragma unroll 1
        for (int r = 0; r < 9; r++) {
            const int di = r / 3, dj = r - (r / 3) * 3;
            const bf16* Ar = Ac + r * 1536;

            uint32_t a[4][4];
#pragma unroll
            for (int mt = 0; mt < 4; mt++) {
                int rowm = mt * 16 + gq;
                const bf16* r0 = Ar + rowm * 24;
                const bf16* r1 = Ar + (rowm + 8) * 24;
                a[mt][0] = *(const uint32_t*)(r0 + 2 * tq);
                a[mt][1] = *(const uint32_t*)(r1 + 2 * tq);
                a[mt][2] = *(const uint32_t*)(r0 + 2 * tq + 8);
                a[mt][3] = *(const uint32_t*)(r1 + 2 * tq + 8);
            }
#pragma unroll
            for (int nt = 0; nt < 8; nt++) {
                int n = wn * 64 + nt * 8 + gq;
                int prow = (n >> 6) + di;
                int pcol = (n & 63) + dj + 7;
                const bf16* pb0 = Pc + (2 * tq) * PST + prow * 72 + pcol;
                uint32_t b0 = pkbf(pb0[0], pb0[PST]);
                uint32_t b1 = pkbf(pb0[8 * PST], pb0[9 * PST]);
#pragma unroll
                for (int mt = 0; mt < 4; mt++)
                    mma_bf16(c[mt][nt], a[mt], b0, b1);
            }
        }
    }

#pragma unroll
    for (int mt = 0; mt < 4; mt++) {
#pragma unroll
        for (int half = 0; half < 2; half++) {
            int co = m0 + mt * 16 + gq + half * 8;
            float bi = bias[co];
#pragma unroll
            for (int nt = 0; nt < 8; nt++) {
                int p = n0 + wn * 64 + nt * 8 + tq * 2;
                float v0 = c[mt][nt][half * 2 + 0] + bi;
                float v1 = c[mt][nt][half * 2 + 1] + bi;
                v0 = v0 > 0.f ? v0 : 0.1f * v0;
                v1 = v1 > 0.f ? v1 : 0.1f * v1;
                __nv_bfloat162 o;
                o.x = __float2bfloat16(v0);
                o.y = __float2bfloat16(v1);
                *(__nv_bfloat162*)&Y[((size_t)b * CH + co) * HWP + p] = o;
            }
        }
    }
}

// ============================================================
// prep: convert weights to bf16 (+ reorder ws1 -> [r][co][ci])
// ============================================================
__global__ void prep_weights(
    const float* __restrict__ w0, const float* __restrict__ w1,
    const float* __restrict__ ws0, const float* __restrict__ ws1,
    const float* __restrict__ wo,
    bf16* __restrict__ w0b, bf16* __restrict__ w1b,
    bf16* __restrict__ wsxb, bf16* __restrict__ wob,
    bf16* __restrict__ wrb)
{
    const int S = CH * CH;
    int idx = blockIdx.x * 256 + threadIdx.x;
    if (idx < S) {
        w0b[idx] = __float2bfloat16(w0[idx]);
    } else if (idx < 2 * S) {
        int i = idx - S;
        w1b[i] = __float2bfloat16(w1[i]);
    } else if (idx < 3 * S) {
        int i = idx - 2 * S;
        int co = i / CH, ci = i % CH;
        wsxb[i] = __float2bfloat16(ws0[(size_t)co * (2 * CH) + ci]);
    } else if (idx < 4 * S) {
        int i = idx - 3 * S;
        wob[i] = __float2bfloat16(wo[i]);
    } else if (idx < 4 * S + 9 * S) {
        int i = idx - 4 * S;
        int ci = i % CH;
        int co = (i / CH) % CH;
        int r  = i / S;
        wrb[i] = __float2bfloat16(ws1[((size_t)co * CH + ci) * 9 + r]);
    }
}

// ============================================================
// T[b,m,co] = sum_ci ws0[co, 192+ci] * list_center[b,m,ci]
// ============================================================
__global__ __launch_bounds__(256) void tgen_kernel(
    const float* __restrict__ lc, const float* __restrict__ ws0,
    float* __restrict__ T)
{
    __shared__ float cvec[CH];
    const int bm = blockIdx.x;
    const int cg = blockIdx.y;
    const int tid = threadIdx.x;
    if (tid < CH) cvec[tid] = lc[(size_t)bm * CH + tid];
    __syncthreads();
    const int warp = tid >> 5, lane = tid & 31;
    const int co0 = cg * 32 + warp * 4;
#pragma unroll
    for (int q = 0; q < 4; q++) {
        const float* w = ws0 + (size_t)(co0 + q) * (2 * CH) + CH;
        float s = 0.f;
#pragma unroll
        for (int j = lane; j < CH; j += 32) s = fmaf(w[j], cvec[j], s);
#pragma unroll
        for (int o = 16; o; o >>= 1) s += __shfl_xor_sync(0xffffffffu, s, o);
        if (lane == 0) T[bm * CH + co0 + q] = s;
    }
}

// ============================================================
// Fused depthwise-3x3 (k_sp) + dynamic conv + mean reduce. bf16 I/O.
// ============================================================
__global__ __launch_bounds__(256) void dyn_kernel(
    const bf16* __restrict__ Y1, const bf16* __restrict__ Xf,
    const float* __restrict__ ws2, const float* __restrict__ bs2,
    bf16* __restrict__ Out, float* __restrict__ Mean)
{
    __shared__ float sy[66 * 66];
    __shared__ float sx[66 * 66];
    __shared__ float taps[81];
    __shared__ float tb[9];
    __shared__ float red[256];

    const int c = blockIdx.x;
    const int b = blockIdx.y;
    const int tid = threadIdx.x;

    const bf16* y1p = Y1 + ((size_t)b * CH + c) * HWP;
    const bf16* xp  = Xf + ((size_t)b * CH + c) * HWP;

    for (int idx = tid; idx < 66 * 66; idx += 256) {
        int hh = idx / 66 - 1;
        int ww = idx % 66 - 1;
        bool ok = (hh >= 0 && hh < 64 && ww >= 0 && ww < 64);
        sy[idx] = ok ? __bfloat162float(y1p[hh * 64 + ww]) : 0.f;
        sx[idx] = ok ? __bfloat162float(xp[hh * 64 + ww]) : 0.f;
    }
    if (tid < 81) taps[tid] = ws2[c * 81 + tid];
    if (tid < 9)  tb[tid]   = bs2[c * 9 + tid];
    __syncthreads();

    float sum = 0.f;
    for (int pp = tid; pp < HWP; pp += 256) {
        int hq = pp >> 6;
        int wq = pp & 63;
        float ywin[9], xwin[9];
#pragma unroll
        for (int di = 0; di < 3; di++)
#pragma unroll
            for (int dj = 0; dj < 3; dj++) {
                ywin[di * 3 + dj] = sy[(hq + di) * 66 + (wq + dj)];
                xwin[di * 3 + dj] = sx[(hq + di) * 66 + (wq + dj)];
            }
        float o = 0.f;
#pragma unroll
        for (int kk = 0; kk < 9; kk++) {
            float ks = tb[kk];
#pragma unroll
            for (int r = 0; r < 9; r++)
                ks = fmaf(ywin[r], taps[kk * 9 + r], ks);
            o = fmaf(xwin[kk], ks, o);
        }
        Out[((size_t)b * CH + c) * HWP + pp] = __float2bfloat16(o);
        sum += o;
    }
    red[tid] = sum;
    __syncthreads();
    for (int s = 128; s > 0; s >>= 1) {
        if (tid < s) red[tid] += red[tid + s];
        __syncthreads();
    }
    if (tid == 0) Mean[b * CH + c] = red[0] * (1.f / HWP);
}

// ============================================================
// SE gate (one block per batch element)
// ============================================================
__global__ __launch_bounds__(192) void se_kernel(
    const float* __restrict__ Mean,
    const float* __restrict__ wc0, const float* __restrict__ bc0,
    const float* __restrict__ wc1, const float* __restrict__ bc1,
    float* __restrict__ Gate)
{
    __shared__ float m[CH];
    __shared__ float hbuf[CH];
    const int b = blockIdx.x;
    const int i = threadIdx.x;
    m[i] = Mean[b * CH + i];
    __syncthreads();
    float s = bc0[i];
    const float* w = wc0 + (size_t)i * CH;
#pragma unroll 8
    for (int j = 0; j < CH; j++) s = fmaf(w[j], m[j], s);
    hbuf[i] = s > 0.f ? s : 0.1f * s;
    __syncthreads();
    float s2 = bc1[i];
    const float* w2 = wc1 + (size_t)i * CH;
#pragma unroll 8
    for (int j = 0; j < CH; j++) s2 = fmaf(w2[j], hbuf[j], s2);
    Gate[b * CH + i] = 1.f / (1.f + expf(-s2));
}

extern "C" void kernel_launch(void* const* d_in, const int* in_sizes, int n_in,
                              void* d_out, int out_size)
{
    const float* input = (const float*)d_in[0];
    const float* lc    = (const float*)d_in[1];
    const int*   mask  = (const int*)d_in[2];
    const float* w0  = (const float*)d_in[3];
    const float* b0  = (const float*)d_in[4];
    const float* w1  = (const float*)d_in[5];
    const float* b1  = (const float*)d_in[6];
    const float* ws0 = (const float*)d_in[7];
    const float* bs0 = (const float*)d_in[8];
    const float* ws1 = (const float*)d_in[9];
    const float* bs1 = (const float*)d_in[10];
    const float* ws2 = (const float*)d_in[11];
    const float* bs2 = (const float*)d_in[12];
    const float* wc0 = (const float*)d_in[13];
    const float* bc0 = (const float*)d_in[14];
    const float* wc1 = (const float*)d_in[15];
    const float* bc1 = (const float*)d_in[16];
    const float* wo  = (const float*)d_in[17];
    const float* bo  = (const float*)d_in[18];
    float* out = (float*)d_out;

    bf16 *pb0, *pb1, *pb2, *pb3, *pw0b, *pw1b, *pwsxb, *pwob, *pwrb;
    float *pT, *pMean, *pGate;
    cudaGetSymbolAddress((void**)&pb0, g_b0);
    cudaGetSymbolAddress((void**)&pb1, g_b1);
    cudaGetSymbolAddress((void**)&pb2, g_b2);
    cudaGetSymbolAddress((void**)&pb3, g_b3);
    cudaGetSymbolAddress((void**)&pw0b, g_w0b);
    cudaGetSymbolAddress((void**)&pw1b, g_w1b);
    cudaGetSymbolAddress((void**)&pwsxb, g_wsxb);
    cudaGetSymbolAddress((void**)&pwob, g_wob);
    cudaGetSymbolAddress((void**)&pwrb, g_wrb);
    cudaGetSymbolAddress((void**)&pT, g_T);
    cudaGetSymbolAddress((void**)&pMean, g_mean);
    cudaGetSymbolAddress((void**)&pGate, g_gate);

    const int conv_smem  = (2 * 13824 + 2 * PSTAGE) * 2;          // 101,888 B
    const int chain_smem = (2 * BBUF + 64 * AST) * 2;             // 228,352 B
    cudaFuncSetAttribute(conv3x3_tc,
                         cudaFuncAttributeMaxDynamicSharedMemorySize, conv_smem);
    cudaFuncSetAttribute(chain3_tc,
                         cudaFuncAttributeMaxDynamicSharedMemorySize, chain_smem);

    dim3 blk(256);

    // 0) prep weights (bf16 + reorder)
    prep_weights<<<(13 * CH * CH + 255) / 256, 256>>>(
        w0, w1, ws0, ws1, wo, pw0b, pw1b, pwsxb, pwob, pwrb);
    // 1) T table
    tgen_kernel<<<dim3(BSZ * MASKN, 6), 256>>>(lc, ws0, pT);
    // 2) fused chain: v -> x -> y0  (x to g_b1, y0 to g_b2)
    chain3_tc<<<dim3(16, 1, 8), blk, chain_smem>>>(
        input, pw0b, pw1b, pwsxb, b0, b1, bs0, mask, pT, pb1, pb2);
    // 3) y1 = lrelu(conv3x3(y0, ws1, bs1))
    conv3x3_tc<<<dim3(8, 3, 8), blk, conv_smem>>>(pb2, pwrb, bs1, pb3);
    // 4) out_feat = dynamic_conv(x, depthwise(y1)) ; per-(b,c) mean
    dyn_kernel<<<dim3(CH, BSZ), 256>>>(pb3, pb1, ws2, bs2, pb0, pMean);
    // 5) gate
    se_kernel<<<BSZ, 192>>>(pMean, wc0, bc0, wc1, bc1, pGate);
    // 6) out = conv1x1(gate*out_feat, wo, bo) + input
    gemm1x1_tc<false, false, true><<<dim3(16, 3, 8), blk>>>(
        pb0, pwob, bo, out, nullptr, nullptr, pGate, input);
}

// round 7
// speedup vs baseline: 6.3050x; 1.0427x over previous
#include <cuda_runtime.h>
#include <cuda_bf16.h>
#include <math.h>
#include <stdint.h>

#define BSZ 8
#define CH 192
#define HWP 4096
#define MASKN 16

typedef __nv_bfloat16 bf16;

// ---- scratch (static device globals) ----
__device__ bf16 g_b0[BSZ * CH * HWP];    // dyn-conv output
__device__ bf16 g_b1[BSZ * CH * HWP];    // x
__device__ bf16 g_b2[BSZ * CH * HWP];    // y0 (channel-pair interleaved!)
__device__ bf16 g_b3[BSZ * CH * HWP];    // y1
__device__ bf16 g_w0b[CH * CH];
__device__ bf16 g_w1b[CH * CH];
__device__ bf16 g_wsxb[CH * CH];         // x-half of ws0
__device__ bf16 g_wob[CH * CH];
__device__ bf16 g_wrb[9 * CH * CH];      // reordered ws1: [r][co][ci]
__device__ float g_T[BSZ * MASKN * CH];
__device__ float g_mean[BSZ * CH];
__device__ float g_gate[BSZ * CH];

// ---- bf16 mma m16n8k16 (row.col), fp32 accumulate ----
__device__ __forceinline__ void mma_bf16(float* c, const uint32_t* a, uint32_t b0, uint32_t b1)
{
    asm("mma.sync.aligned.m16n8k16.row.col.f32.bf16.bf16.f32 "
        "{%0,%1,%2,%3}, {%4,%5,%6,%7}, {%8,%9}, {%0,%1,%2,%3};\n"
        : "+f"(c[0]), "+f"(c[1]), "+f"(c[2]), "+f"(c[3])
        : "r"(a[0]), "r"(a[1]), "r"(a[2]), "r"(a[3]), "r"(b0), "r"(b1));
}

#define LDMX2T(b0, b1, addr) \
    asm volatile("ldmatrix.sync.aligned.m8n8.x2.trans.shared.b16 {%0,%1}, [%2];\n" \
                 : "=r"(b0), "=r"(b1) : "r"(addr))

#define LDMX4(r0, r1, r2, r3, addr) \
    asm volatile("ldmatrix.sync.aligned.m8n8.x4.shared.b16 {%0,%1,%2,%3}, [%4];\n" \
                 : "=r"(r0), "=r"(r1), "=r"(r2), "=r"(r3) : "r"(addr))

#define CP16(dst, src) \
    asm volatile("cp.async.cg.shared.global [%0], [%1], 16;\n" :: "r"(dst), "l"(src))
#define CP_COMMIT() asm volatile("cp.async.commit_group;\n")
#define CP_WAIT0()  asm volatile("cp.async.wait_group 0;\n")

// ============================================================
// Fused chain: v = lrelu(W0@in), x = W1@v, y0 = lrelu(Wsx@x + T + bs0)
// Activation tile resident in SMEM (ping-pong). y0 written to global in
// channel-pair-interleaved layout [b][co/2][pixel][2] for the conv.
// grid (16, 1, 8), 256 threads.
// ============================================================
#define BST 264            // B row stride in halves
#define BBUF (CH * BST)
#define AST 200            // A row stride in halves (400B, 16-mult)

__global__ __launch_bounds__(256) void chain3_tc(
    const float* __restrict__ input,
    const bf16* __restrict__ W0, const bf16* __restrict__ W1,
    const bf16* __restrict__ Wsx,
    const float* __restrict__ bias0, const float* __restrict__ bias1,
    const float* __restrict__ bias2,
    const int* __restrict__ mask, const float* __restrict__ Tt,
    bf16* __restrict__ Xout, bf16* __restrict__ Y0i)
{
    extern __shared__ __align__(16) bf16 sm[];
    bf16* Bbuf0 = sm;
    bf16* Bbuf1 = sm + BBUF;
    bf16* As    = sm + 2 * BBUF;

    const int b   = blockIdx.z;
    const int n0  = blockIdx.x * 256;
    const int tid = threadIdx.x;
    const int lane = tid & 31;
    const int warp = tid >> 5;
    const int wm = warp >> 2;
    const int wn = warp & 3;
    const int tq = lane & 3;
    const int gq = lane >> 2;
    // ldmatrix per-lane row select
    const int lg = lane >> 3;
    const int arow = (lg & 1) * 8 + (lane & 7);
    const int akoff = (lg >> 1) * 8;

    const float* inb = input + (size_t)b * CH * HWP;
    for (int idx = tid; idx < CH * 128; idx += 256) {
        int ch = idx >> 7, pu = idx & 127;
        float2 v = *(const float2*)(inb + (size_t)ch * HWP + n0 + 2 * pu);
        __nv_bfloat162 o;
        o.x = __float2bfloat16(v.x);
        o.y = __float2bfloat16(v.y);
        *(__nv_bfloat162*)(Bbuf0 + ch * BST + 2 * pu) = o;
    }
    __syncthreads();

    uint32_t s_as = (uint32_t)__cvta_generic_to_shared(As);

#pragma unroll 1
    for (int ph = 0; ph < 3; ph++) {
        const bf16* W = (ph == 0) ? W0 : (ph == 1 ? W1 : Wsx);
        const float* bias = (ph == 0) ? bias0 : (ph == 1 ? bias1 : bias2);
        bf16* Bsrc = (ph == 1) ? Bbuf1 : Bbuf0;
        bf16* Bdst = (ph == 0) ? Bbuf1 : Bbuf0;
        uint32_t s_bsrc = (uint32_t)__cvta_generic_to_shared(Bsrc);

#pragma unroll 1
        for (int mc = 0; mc < 3; mc++) {
            const int m0 = mc * 64;

#pragma unroll
            for (int t = 0; t < 6; t++) {
                int idx = tid + t * 256;
                int i = idx / 24, c8 = (idx % 24) * 8;
                CP16(s_as + (uint32_t)(i * AST + c8) * 2,
                     W + (size_t)(m0 + i) * CH + c8);
            }
            CP_COMMIT();
            CP_WAIT0();
            __syncthreads();

            float c[2][8][4];
#pragma unroll
            for (int i = 0; i < 2; i++)
#pragma unroll
                for (int j = 0; j < 8; j++)
#pragma unroll
                    for (int q = 0; q < 4; q++) c[i][j][q] = 0.f;

#pragma unroll
            for (int kt = 0; kt < CH; kt += 16) {
                uint32_t a[2][4];
#pragma unroll
                for (int mt = 0; mt < 2; mt++) {
                    uint32_t aadr = s_as
                        + (uint32_t)((wm * 32 + mt * 16 + arow) * AST + kt + akoff) * 2;
                    LDMX4(a[mt][0], a[mt][1], a[mt][2], a[mt][3], aadr);
                }
                uint32_t badr = s_bsrc
                    + (uint32_t)((kt + (lane & 15)) * BST + wn * 64) * 2;
#pragma unroll
                for (int nt = 0; nt < 8; nt++) {
                    uint32_t bf0, bf1;
                    LDMX2T(bf0, bf1, badr + nt * 16);
                    mma_bf16(c[0][nt], a[0], bf0, bf1);
                    mma_bf16(c[1][nt], a[1], bf0, bf1);
                }
            }

#pragma unroll
            for (int mt = 0; mt < 2; mt++) {
#pragma unroll
                for (int half = 0; half < 2; half++) {
                    int co = m0 + wm * 32 + mt * 16 + gq + half * 8;
                    float bi = bias[co];
#pragma unroll
                    for (int nt = 0; nt < 8; nt++) {
                        int ploc = wn * 64 + nt * 8 + tq * 2;
                        float v0 = c[mt][nt][half * 2 + 0] + bi;
                        float v1 = c[mt][nt][half * 2 + 1] + bi;
                        if (ph == 2) {
                            int p = n0 + ploc;
                            int mk0 = mask[b * HWP + p];
                            int mk1 = mask[b * HWP + p + 1];
                            v0 += Tt[(b * MASKN + mk0) * CH + co];
                            v1 += Tt[(b * MASKN + mk1) * CH + co];
                        }
                        if (ph != 1) {
                            v0 = v0 > 0.f ? v0 : 0.1f * v0;
                            v1 = v1 > 0.f ? v1 : 0.1f * v1;
                        }
                        if (ph < 2) {
                            __nv_bfloat162 o;
                            o.x = __float2bfloat16(v0);
                            o.y = __float2bfloat16(v1);
                            *(__nv_bfloat162*)(Bdst + co * BST + ploc) = o;
                        }
                        if (ph == 1) {
                            __nv_bfloat162 o;
                            o.x = __float2bfloat16(v0);
                            o.y = __float2bfloat16(v1);
                            *(__nv_bfloat162*)(Xout + ((size_t)b * CH + co) * HWP + n0 + ploc) = o;
                        }
                        if (ph == 2) {
                            // interleaved: word (b*96 + co/2)*HWP + p ; half co&1
                            size_t w = ((size_t)b * (CH / 2) + (co >> 1)) * HWP + n0 + ploc;
                            bf16* dst = Y0i + w * 2 + (co & 1);
                            dst[0] = __float2bfloat16(v0);
                            dst[2] = __float2bfloat16(v1);
                        }
                    }
                }
            }
            __syncthreads();
        }
    }
}

// ============================================================
// FINAL 1x1 conv GEMM (gate folded into A; fp32 out + residual).
// ============================================================
__global__ __launch_bounds__(256) void gemm_final_tc(
    const bf16* __restrict__ X, const bf16* __restrict__ Wb,
    const float* __restrict__ bias, float* __restrict__ Y,
    const float* __restrict__ gate, const float* __restrict__ resid)
{
    __shared__ __align__(16) bf16 As[2][64][24];
    __shared__ __align__(16) bf16 Bs[2][16][264];
    __shared__ float sgate[CH];

    const int b   = blockIdx.z;
    const int m0  = blockIdx.y * 64;
    const int n0  = blockIdx.x * 256;
    const int tid = threadIdx.x;
    const int lane = tid & 31;
    const int warp = tid >> 5;
    const int wm = warp >> 2;
    const int wn = warp & 3;
    const int tq = lane & 3;
    const int gq = lane >> 2;
    const int lg = lane >> 3;
    const int arow = (lg & 1) * 8 + (lane & 7);
    const int akoff = (lg >> 1) * 8;

    const bf16* Xb = X + (size_t)b * CH * HWP;

    if (tid < CH) sgate[tid] = gate[b * CH + tid];
    __syncthreads();

    uint32_t s_as = (uint32_t)__cvta_generic_to_shared(&As[0][0][0]);
    uint32_t s_bs = (uint32_t)__cvta_generic_to_shared(&Bs[0][0][0]);

    float c[2][8][4];
#pragma unroll
    for (int i = 0; i < 2; i++)
#pragma unroll
        for (int j = 0; j < 8; j++)
#pragma unroll
            for (int q = 0; q < 4; q++) c[i][j][q] = 0.f;

    auto issue = [&](int kt, int st) {
        if (tid < 128) {
            int co = tid >> 1, h8 = (tid & 1) * 8;
            const bf16* src = Wb + (size_t)(m0 + co) * CH + kt + h8;
            bf16 tmp[8];
            *(uint4*)tmp = *(const uint4*)src;
            bf16 dst8[8];
#pragma unroll
            for (int i = 0; i < 8; i++)
                dst8[i] = __float2bfloat16(__bfloat162float(tmp[i]) * sgate[kt + h8 + i]);
            *(uint4*)&As[st][co][h8] = *(uint4*)dst8;
        }
#pragma unroll
        for (int t = 0; t < 2; t++) {
            int idx = tid + t * 256;
            int k = idx >> 5, q = idx & 31;
            CP16(s_bs + (uint32_t)(st * 4224 + k * 264 + q * 8) * 2,
                 Xb + (size_t)(kt + k) * HWP + n0 + q * 8);
        }
    };

    issue(0, 0);
    CP_COMMIT();

    for (int step = 0; step < 12; step++) {
        CP_WAIT0();
        __syncthreads();
        if (step < 11) { issue((step + 1) * 16, (step + 1) & 1); CP_COMMIT(); }

        uint32_t sAc = s_as + (step & 1) * 1536 * 2;
        uint32_t sBc = s_bs + (step & 1) * 4224 * 2;

        uint32_t a[2][4];
#pragma unroll
        for (int mt = 0; mt < 2; mt++) {
            uint32_t aadr = sAc + (uint32_t)((wm * 32 + mt * 16 + arow) * 24 + akoff) * 2;
            LDMX4(a[mt][0], a[mt][1], a[mt][2], a[mt][3], aadr);
        }
        uint32_t badr = sBc + (uint32_t)((lane & 15) * 264 + wn * 64) * 2;
#pragma unroll
        for (int nt = 0; nt < 8; nt++) {
            uint32_t b0, b1;
            LDMX2T(b0, b1, badr + nt * 16);
            mma_bf16(c[0][nt], a[0], b0, b1);
            mma_bf16(c[1][nt], a[1], b0, b1);
        }
    }

#pragma unroll
    for (int mt = 0; mt < 2; mt++) {
#pragma unroll
        for (int half = 0; half < 2; half++) {
            int co = m0 + wm * 32 + mt * 16 + gq + half * 8;
            float bi = bias[co];
#pragma unroll
            for (int nt = 0; nt < 8; nt++) {
                int p = n0 + wn * 64 + nt * 8 + tq * 2;
                size_t off = ((size_t)b * CH + co) * HWP + p;
                float v0 = c[mt][nt][half * 2 + 0] + bi + resid[off];
                float v1 = c[mt][nt][half * 2 + 1] + bi + resid[off + 1];
                *(float2*)(Y + off) = make_float2(v0, v1);
            }
        }
    }
}

// ============================================================
// 3x3 conv, bf16 TC. B patch is channel-pair interleaved: plane m holds
// channels {kt+2m, kt+2m+1}, one uint32 word per pixel. B fragment =
// 2 LDS.32 (conflict-free). A fragments via ldmatrix.x4.
// Patch: [8 planes][10 rows][72 words], plane stride 728 words.
// Data at word cols 8..71; pads stay zero (memset once).
// ============================================================
#define PSTW 728                  // words per plane
#define PSTAGEW (8 * PSTW)        // 5824 words per stage
__global__ __launch_bounds__(256) void conv3x3_tc(
    const bf16* __restrict__ Y0i, const bf16* __restrict__ Wr,
    const float* __restrict__ bias, bf16* __restrict__ Y)
{
    extern __shared__ __align__(16) bf16 smem[];
    bf16* Asb = smem;                           // [2][9][64][24] halves
    uint32_t* Psb = (uint32_t*)(smem + 2 * 13824);  // [2][PSTAGEW] words

    const int b    = blockIdx.z;
    const int m0   = blockIdx.y * 64;
    const int tile = blockIdx.x;
    const int row0 = tile * 8;
    const int n0   = tile * 512;
    const int tid  = threadIdx.x;
    const int lane = tid & 31;
    const int wn   = tid >> 5;
    const int tq = lane & 3;
    const int gq = lane >> 2;
    const int lg = lane >> 3;
    const int arow = (lg & 1) * 8 + (lane & 7);
    const int akoff = (lg >> 1) * 8;

    const uint32_t* Xw = (const uint32_t*)Y0i + (size_t)b * (CH / 2) * HWP;

    for (int i = tid; i < 2 * PSTAGEW; i += 256) Psb[i] = 0u;
    __syncthreads();

    uint32_t s_as = (uint32_t)__cvta_generic_to_shared(Asb);
    uint32_t s_ps = (uint32_t)__cvta_generic_to_shared(Psb);

    float c[4][8][4];
#pragma unroll
    for (int i = 0; i < 4; i++)
#pragma unroll
        for (int j = 0; j < 8; j++)
#pragma unroll
            for (int q = 0; q < 4; q++) c[i][j][q] = 0.f;

    auto issue = [&](int kt, int st) {
        uint32_t ab = s_as + st * (13824 * 2);
#pragma unroll
        for (int t = 0; t < 5; t++) {
            int idx = tid + t * 256;
            if (idx < 1152) {
                int r = idx >> 7;
                int rem = idx & 127;
                int co = rem >> 1, h8 = (rem & 1) * 8;
                CP16(ab + (uint32_t)((r * 64 + co) * 24 + h8) * 2,
                     Wr + ((size_t)r * CH + m0 + co) * CH + kt + h8);
            }
        }
        uint32_t pb = s_ps + st * (PSTAGEW * 4);
        const int cp0 = kt >> 1;
#pragma unroll
        for (int t = 0; t < 5; t++) {      // 8 planes * 10 rows * 16 qgroups
            int idx = tid + t * 256;
            int m = idx / 160;
            int rem = idx - m * 160;
            int rr = rem >> 4;
            int q  = rem & 15;
            int hh = row0 + rr - 1;
            if (hh >= 0 && hh < 64) {
                CP16(pb + (uint32_t)(m * PSTW + rr * 72 + 8 + q * 4) * 4,
                     Xw + (size_t)(cp0 + m) * HWP + hh * 64 + q * 4);
            }
        }
    };

    issue(0, 0);
    CP_COMMIT();

    for (int step = 0; step < 12; step++) {
        CP_WAIT0();
        __syncthreads();
        if (step < 11) { issue((step + 1) * 16, (step + 1) & 1); CP_COMMIT(); }

        uint32_t sAc = s_as + (step & 1) * (13824 * 2);
        const uint32_t* Pw = Psb + (step & 1) * PSTAGEW;

#pragma unroll 1
        for (int r = 0; r < 9; r++) {
            const int di = r / 3, dj = r - (r / 3) * 3;

            uint32_t a[4][4];
#pragma unroll
            for (int mt = 0; mt < 4; mt++) {
                uint32_t aadr = sAc
                    + (uint32_t)((r * 64 + mt * 16 + arow) * 24 + akoff) * 2;
                LDMX4(a[mt][0], a[mt][1], a[mt][2], a[mt][3], aadr);
            }
            const uint32_t* pr0 = Pw + tq * PSTW + (wn + di) * 72 + gq + dj + 7;
            const uint32_t* pr1 = pr0 + 4 * PSTW;
#pragma unroll
            for (int nt = 0; nt < 8; nt++) {
                uint32_t b0 = pr0[nt * 8];
                uint32_t b1 = pr1[nt * 8];
#pragma unroll
                for (int mt = 0; mt < 4; mt++)
                    mma_bf16(c[mt][nt], a[mt], b0, b1);
            }
        }
    }

#pragma unroll
    for (int mt = 0; mt < 4; mt++) {
#pragma unroll
        for (int half = 0; half < 2; half++) {
            int co = m0 + mt * 16 + gq + half * 8;
            float bi = bias[co];
#pragma unroll
            for (int nt = 0; nt < 8; nt++) {
                int p = n0 + wn * 64 + nt * 8 + tq * 2;
                float v0 = c[mt][nt][half * 2 + 0] + bi;
                float v1 = c[mt][nt][half * 2 + 1] + bi;
                v0 = v0 > 0.f ? v0 : 0.1f * v0;
                v1 = v1 > 0.f ? v1 : 0.1f * v1;
                __nv_bfloat162 o;
                o.x = __float2bfloat16(v0);
                o.y = __float2bfloat16(v1);
                *(__nv_bfloat162*)&Y[((size_t)b * CH + co) * HWP + p] = o;
            }
        }
    }
}

// ============================================================
// prep: convert weights to bf16 (+ reorder ws1 -> [r][co][ci])
// ============================================================
__global__ void prep_weights(
    const float* __restrict__ w0, const float* __restrict__ w1,
    const float* __restrict__ ws0, const float* __restrict__ ws1,
    const float* __restrict__ wo,
    bf16* __restrict__ w0b, bf16* __restrict__ w1b,
    bf16* __restrict__ wsxb, bf16* __restrict__ wob,
    bf16* __restrict__ wrb)
{
    const int S = CH * CH;
    int idx = blockIdx.x * 256 + threadIdx.x;
    if (idx < S) {
        w0b[idx] = __float2bfloat16(w0[idx]);
    } else if (idx < 2 * S) {
        int i = idx - S;
        w1b[i] = __float2bfloat16(w1[i]);
    } else if (idx < 3 * S) {
        int i = idx - 2 * S;
        int co = i / CH, ci = i % CH;
        wsxb[i] = __float2bfloat16(ws0[(size_t)co * (2 * CH) + ci]);
    } else if (idx < 4 * S) {
        int i = idx - 3 * S;
        wob[i] = __float2bfloat16(wo[i]);
    } else if (idx < 4 * S + 9 * S) {
        int i = idx - 4 * S;
        int ci = i % CH;
        int co = (i / CH) % CH;
        int r  = i / S;
        wrb[i] = __float2bfloat16(ws1[((size_t)co * CH + ci) * 9 + r]);
    }
}

// ============================================================
// T[b,m,co] = sum_ci ws0[co, 192+ci] * list_center[b,m,ci]
// ============================================================
__global__ __launch_bounds__(256) void tgen_kernel(
    const float* __restrict__ lc, const float* __restrict__ ws0,
    float* __restrict__ T)
{
    __shared__ float cvec[CH];
    const int bm = blockIdx.x;
    const int cg = blockIdx.y;
    const int tid = threadIdx.x;
    if (tid < CH) cvec[tid] = lc[(size_t)bm * CH + tid];
    __syncthreads();
    const int warp = tid >> 5, lane = tid & 31;
    const int co0 = cg * 32 + warp * 4;
#pragma unroll
    for (int q = 0; q < 4; q++) {
        const float* w = ws0 + (size_t)(co0 + q) * (2 * CH) + CH;
        float s = 0.f;
#pragma unroll
        for (int j = lane; j < CH; j += 32) s = fmaf(w[j], cvec[j], s);
#pragma unroll
        for (int o = 16; o; o >>= 1) s += __shfl_xor_sync(0xffffffffu, s, o);
        if (lane == 0) T[bm * CH + co0 + q] = s;
    }
}

// ============================================================
// Fused depthwise-3x3 (k_sp) + dynamic conv + mean reduce. bf16 I/O.
// ============================================================
__global__ __launch_bounds__(256) void dyn_kernel(
    const bf16* __restrict__ Y1, const bf16* __restrict__ Xf,
    const float* __restrict__ ws2, const float* __restrict__ bs2,
    bf16* __restrict__ Out, float* __restrict__ Mean)
{
    __shared__ float sy[66 * 66];
    __shared__ float sx[66 * 66];
    __shared__ float taps[81];
    __shared__ float tb[9];
    __shared__ float red[256];

    const int c = blockIdx.x;
    const int b = blockIdx.y;
    const int tid = threadIdx.x;

    const bf16* y1p = Y1 + ((size_t)b * CH + c) * HWP;
    const bf16* xp  = Xf + ((size_t)b * CH + c) * HWP;

    for (int idx = tid; idx < 66 * 66; idx += 256) {
        int hh = idx / 66 - 1;
        int ww = idx % 66 - 1;
        bool ok = (hh >= 0 && hh < 64 && ww >= 0 && ww < 64);
        sy[idx] = ok ? __bfloat162float(y1p[hh * 64 + ww]) : 0.f;
        sx[idx] = ok ? __bfloat162float(xp[hh * 64 + ww]) : 0.f;
    }
    if (tid < 81) taps[tid] = ws2[c * 81 + tid];
    if (tid < 9)  tb[tid]   = bs2[c * 9 + tid];
    __syncthreads();

    float sum = 0.f;
    for (int pp = tid; pp < HWP; pp += 256) {
        int hq = pp >> 6;
        int wq = pp & 63;
        float ywin[9], xwin[9];
#pragma unroll
        for (int di = 0; di < 3; di++)
#pragma unroll
            for (int dj = 0; dj < 3; dj++) {
                ywin[di * 3 + dj] = sy[(hq + di) * 66 + (wq + dj)];
                xwin[di * 3 + dj] = sx[(hq + di) * 66 + (wq + dj)];
            }
        float o = 0.f;
#pragma unroll
        for (int kk = 0; kk < 9; kk++) {
            float ks = tb[kk];
#pragma unroll
            for (int r = 0; r < 9; r++)
                ks = fmaf(ywin[r], taps[kk * 9 + r], ks);
            o = fmaf(xwin[kk], ks, o);
        }
        Out[((size_t)b * CH + c) * HWP + pp] = __float2bfloat16(o);
        sum += o;
    }
    red[tid] = sum;
    __syncthreads();
    for (int s = 128; s > 0; s >>= 1) {
        if (tid < s) red[tid] += red[tid + s];
        __syncthreads();
    }
    if (tid == 0) Mean[b * CH + c] = red[0] * (1.f / HWP);
}

// ============================================================
// SE gate (one block per batch element)
// ============================================================
__global__ __launch_bounds__(192) void se_kernel(
    const float* __restrict__ Mean,
    const float* __restrict__ wc0, const float* __restrict__ bc0,
    const float* __restrict__ wc1, const float* __restrict__ bc1,
    float* __restrict__ Gate)
{
    __shared__ float m[CH];
    __shared__ float hbuf[CH];
    const int b = blockIdx.x;
    const int i = threadIdx.x;
    m[i] = Mean[b * CH + i];
    __syncthreads();
    float s = bc0[i];
    const float* w = wc0 + (size_t)i * CH;
#pragma unroll 8
    for (int j = 0; j < CH; j++) s = fmaf(w[j], m[j], s);
    hbuf[i] = s > 0.f ? s : 0.1f * s;
    __syncthreads();
    float s2 = bc1[i];
    const float* w2 = wc1 + (size_t)i * CH;
#pragma unroll 8
    for (int j = 0; j < CH; j++) s2 = fmaf(w2[j], hbuf[j], s2);
    Gate[b * CH + i] = 1.f / (1.f + expf(-s2));
}

extern "C" void kernel_launch(void* const* d_in, const int* in_sizes, int n_in,
                              void* d_out, int out_size)
{
    const float* input = (const float*)d_in[0];
    const float* lc    = (const float*)d_in[1];
    const int*   mask  = (const int*)d_in[2];
    const float* w0  = (const float*)d_in[3];
    const float* b0  = (const float*)d_in[4];
    const float* w1  = (const float*)d_in[5];
    const float* b1  = (const float*)d_in[6];
    const float* ws0 = (const float*)d_in[7];
    const float* bs0 = (const float*)d_in[8];
    const float* ws1 = (const float*)d_in[9];
    const float* bs1 = (const float*)d_in[10];
    const float* ws2 = (const float*)d_in[11];
    const float* bs2 = (const float*)d_in[12];
    const float* wc0 = (const float*)d_in[13];
    const float* bc0 = (const float*)d_in[14];
    const float* wc1 = (const float*)d_in[15];
    const float* bc1 = (const float*)d_in[16];
    const float* wo  = (const float*)d_in[17];
    const float* bo  = (const float*)d_in[18];
    float* out = (float*)d_out;

    bf16 *pb0, *pb1, *pb2, *pb3, *pw0b, *pw1b, *pwsxb, *pwob, *pwrb;
    float *pT, *pMean, *pGate;
    cudaGetSymbolAddress((void**)&pb0, g_b0);
    cudaGetSymbolAddress((void**)&pb1, g_b1);
    cudaGetSymbolAddress((void**)&pb2, g_b2);
    cudaGetSymbolAddress((void**)&pb3, g_b3);
    cudaGetSymbolAddress((void**)&pw0b, g_w0b);
    cudaGetSymbolAddress((void**)&pw1b, g_w1b);
    cudaGetSymbolAddress((void**)&pwsxb, g_wsxb);
    cudaGetSymbolAddress((void**)&pwob, g_wob);
    cudaGetSymbolAddress((void**)&pwrb, g_wrb);
    cudaGetSymbolAddress((void**)&pT, g_T);
    cudaGetSymbolAddress((void**)&pMean, g_mean);
    cudaGetSymbolAddress((void**)&pGate, g_gate);

    const int conv_smem  = 2 * 13824 * 2 + 2 * PSTAGEW * 4;      // 101,888 B
    const int chain_smem = (2 * BBUF + 64 * AST) * 2;            // 228,352 B
    cudaFuncSetAttribute(conv3x3_tc,
                         cudaFuncAttributeMaxDynamicSharedMemorySize, conv_smem);
    cudaFuncSetAttribute(chain3_tc,
                         cudaFuncAttributeMaxDynamicSharedMemorySize, chain_smem);

    dim3 blk(256);

    // 0) prep weights (bf16 + reorder)
    prep_weights<<<(13 * CH * CH + 255) / 256, 256>>>(
        w0, w1, ws0, ws1, wo, pw0b, pw1b, pwsxb, pwob, pwrb);
    // 1) T table
    tgen_kernel<<<dim3(BSZ * MASKN, 6), 256>>>(lc, ws0, pT);
    // 2) fused chain: v -> x -> y0  (x to g_b1, y0 interleaved to g_b2)
    chain3_tc<<<dim3(16, 1, 8), blk, chain_smem>>>(
        input, pw0b, pw1b, pwsxb, b0, b1, bs0, mask, pT, pb1, pb2);
    // 3) y1 = lrelu(conv3x3(y0, ws1, bs1))
    conv3x3_tc<<<dim3(8, 3, 8), blk, conv_smem>>>(pb2, pwrb, bs1, pb3);
    // 4) out_feat = dynamic_conv(x, depthwise(y1)) ; per-(b,c) mean
    dyn_kernel<<<dim3(CH, BSZ), 256>>>(pb3, pb1, ws2, bs2, pb0, pMean);
    // 5) gate
    se_kernel<<<BSZ, 192>>>(pMean, wc0, bc0, wc1, bc1, pGate);
    // 6) out = conv1x1(gate*out_feat, wo, bo) + input
    gemm_final_tc<<<dim3(16, 3, 8), blk>>>(
        pb0, pwob, bo, out, pGate, input);
}